// round 1
// baseline (speedup 1.0000x reference)
#include <cuda_runtime.h>

#define BB 4
#define NN 4096
#define KNN 9
#define BN_TOT (BB*NN)
#define NEG_INF (-3.402823466e38f)

// ---------------- device scratch (static globals; no allocation) ----------------
__device__ float d_Xt[BN_TOT*3];        // points, row-major (p, 3)
__device__ float d_x2[BN_TOT];          // squared norms
__device__ int   d_idx[BN_TOT*KNN];     // neighbor GLOBAL row indices (b*N+m)
__device__ float d_G[BN_TOT*512];       // GEMM out: per row [U(0..O-1) | Z(O..2O-1)]
__device__ float d_actA[BN_TOT*256];
__device__ float d_actB[BN_TOT*256];
__device__ float d_out1[BN_TOT*64];
__device__ float d_low[BN_TOT*48];
__device__ float d_cat[BN_TOT*304];
__device__ float d_fused[BN_TOT*256];
__device__ float d_wcat[512*256];       // [Wa-Wb ; Wb] stacked (2O x C)
__device__ float d_part1[1024*256];
__device__ float d_part2[1024*256];
__device__ float d_scale[256];
__device__ float d_shift[256];
__device__ float d_pool[4*16*512];
__device__ float d_h[4*512];
__device__ float d_y1[4*256];
__device__ float d_h2[4*256];

// ---------------- prep: transpose x to (p,3) + squared norms ----------------
__global__ void prep_kernel(const float* __restrict__ x, float* __restrict__ Xt,
                            float* __restrict__ x2) {
    int t = blockIdx.x * blockDim.x + threadIdx.x;
    if (t >= BN_TOT) return;
    int b = t / NN, n = t % NN;
    float a0 = x[(b*3+0)*NN + n];
    float a1 = x[(b*3+1)*NN + n];
    float a2 = x[(b*3+2)*NN + n];
    Xt[t*3+0] = a0; Xt[t*3+1] = a1; Xt[t*3+2] = a2;
    x2[t] = a0*a0 + a1*a1 + a2*a2;
}

// ---------------- knn: per-thread top-9 over the batch (smem resident) ----------------
__global__ void knn_kernel(const float* __restrict__ Xt, const float* __restrict__ x2,
                           int* __restrict__ idxOut) {
    extern __shared__ float sm[];
    float* sx = sm;
    float* sy = sm + NN;
    float* sz = sm + 2*NN;
    float* s2 = sm + 3*NN;
    int b = blockIdx.x;
    int n = blockIdx.y * blockDim.x + threadIdx.x;
    const float* Xb = Xt + (size_t)b*NN*3;
    for (int t = threadIdx.x; t < NN; t += blockDim.x) {
        sx[t] = Xb[t*3+0];
        sy[t] = Xb[t*3+1];
        sz[t] = Xb[t*3+2];
        s2[t] = x2[b*NN + t];
    }
    __syncthreads();
    float px = sx[n], py = sy[n], pz = sz[n], p2 = s2[n];
    float bd[KNN]; int bi[KNN];
#pragma unroll
    for (int j = 0; j < KNN; ++j) { bd[j] = 1e30f; bi[j] = 0; }
#pragma unroll 4
    for (int m = 0; m < NN; ++m) {
        float dot = px*sx[m] + py*sy[m] + pz*sz[m];
        float d = p2 + s2[m] - 2.0f*dot;
        if (m == n) d = 1e30f;
        if (d < bd[KNN-1]) {
            float vd = d; int vi = m;
#pragma unroll
            for (int j = 0; j < KNN; ++j) {
                if (vd < bd[j]) {
                    float td = bd[j]; bd[j] = vd; vd = td;
                    int   ti = bi[j]; bi[j] = vi; vi = ti;
                }
            }
        }
    }
#pragma unroll
    for (int j = 0; j < KNN; ++j)
        idxOut[(b*NN + n)*KNN + j] = b*NN + bi[j];
}

// ---------------- weight prep: wcat = [Wa - Wb ; Wb]  (w is O x 2C) ----------------
__global__ void wprep_kernel(const float* __restrict__ w, float* __restrict__ wc,
                             int O, int C) {
    int t = blockIdx.x * blockDim.x + threadIdx.x;
    if (t >= O*C) return;
    int o = t / C, c = t % C;
    float wa = w[o*2*C + c];
    float wb = w[o*2*C + C + c];
    wc[o*C + c]       = wa - wb;
    wc[(O+o)*C + c]   = wb;
}

// ---------------- SGEMM: Out[M x Nc] = A[M x Kc] * W[Nc x Kc]^T ----------------
#define TBM 128
#define TBN 128
#define TBK 16
__global__ void sgemm_kernel(const float* __restrict__ A, const float* __restrict__ W,
                             float* __restrict__ C, int M, int Nc, int Kc) {
    __shared__ float As[TBK][TBM+4];
    __shared__ float Bs[TBK][TBN+4];
    int tid = threadIdx.x;
    int bm = blockIdx.x * TBM;
    int bn = blockIdx.y * TBN;
    int tx = tid % 16;           // output col group
    int ty = tid / 16;           // output row group
    int loadRow = tid / 16;      // 0..15
    int loadCol = tid % 16;      // k 0..15
    float acc[8][8];
#pragma unroll
    for (int i = 0; i < 8; ++i)
#pragma unroll
        for (int j = 0; j < 8; ++j) acc[i][j] = 0.0f;

    for (int k0 = 0; k0 < Kc; k0 += TBK) {
        int k = k0 + loadCol;
        bool kok = (k < Kc);
#pragma unroll
        for (int r = 0; r < 8; ++r) {
            int m = bm + loadRow + r*16;
            As[loadCol][loadRow + r*16] = (kok && m < M) ? A[(size_t)m*Kc + k] : 0.0f;
        }
#pragma unroll
        for (int r = 0; r < 8; ++r) {
            int n = bn + loadRow + r*16;
            Bs[loadCol][loadRow + r*16] = (kok && n < Nc) ? W[(size_t)n*Kc + k] : 0.0f;
        }
        __syncthreads();
#pragma unroll
        for (int kk = 0; kk < TBK; ++kk) {
            float ra[8], rb[8];
            float4 a0 = *(const float4*)&As[kk][ty*8];
            float4 a1 = *(const float4*)&As[kk][ty*8+4];
            float4 b0 = *(const float4*)&Bs[kk][tx*8];
            float4 b1 = *(const float4*)&Bs[kk][tx*8+4];
            ra[0]=a0.x; ra[1]=a0.y; ra[2]=a0.z; ra[3]=a0.w;
            ra[4]=a1.x; ra[5]=a1.y; ra[6]=a1.z; ra[7]=a1.w;
            rb[0]=b0.x; rb[1]=b0.y; rb[2]=b0.z; rb[3]=b0.w;
            rb[4]=b1.x; rb[5]=b1.y; rb[6]=b1.z; rb[7]=b1.w;
#pragma unroll
            for (int i = 0; i < 8; ++i)
#pragma unroll
                for (int j = 0; j < 8; ++j)
                    acc[i][j] = fmaf(ra[i], rb[j], acc[i][j]);
        }
        __syncthreads();
    }
#pragma unroll
    for (int i = 0; i < 8; ++i) {
        int m = bm + ty*8 + i;
        if (m < M) {
#pragma unroll
            for (int j = 0; j < 8; ++j) {
                int n = bn + tx*8 + j;
                if (n < Nc) C[(size_t)m*Nc + n] = acc[i][j];
            }
        }
    }
}

// ---------------- edge pass: M = U + max_k Z[nbr]; per-channel edge stats ----------------
// G rows: [U(0..O-1) | Z(O..2O-1)], stride 2O. Writes M in place over U.
// blockDim = O, each block handles 16 points; partial sums -> part1/part2 (deterministic).
__global__ void edge_kernel(float* __restrict__ G, const int* __restrict__ idx,
                            int O, float* __restrict__ part1, float* __restrict__ part2) {
    int o = threadIdx.x;
    int blk = blockIdx.x;
    int p0 = blk * 16;
    __shared__ int sidx[16*KNN];
    for (int t = threadIdx.x; t < 16*KNN; t += blockDim.x)
        sidx[t] = idx[p0*KNN + t];
    __syncthreads();
    int S = 2*O;
    float s1 = 0.0f, s2 = 0.0f;
    for (int pp = 0; pp < 16; ++pp) {
        int p = p0 + pp;
        float u = G[(size_t)p*S + o];
        float zmax = NEG_INF;
#pragma unroll
        for (int k = 0; k < KNN; ++k) {
            int j = sidx[pp*KNN + k];
            float z = G[(size_t)j*S + O + o];
            float v = u + z;
            zmax = fmaxf(zmax, z);
            s1 += v;
            s2 += v*v;
        }
        G[(size_t)p*S + o] = u + zmax;
    }
    part1[blk*O + o] = s1;
    part2[blk*O + o] = s2;
}

// ---------------- deterministic stats reduce over 1024 blocks -> scale/shift ----------------
__global__ void reduce_stats_kernel(const float* __restrict__ part1,
                                    const float* __restrict__ part2,
                                    const float* __restrict__ g, const float* __restrict__ b,
                                    int O, float invCnt) {
    int o = threadIdx.x;
    float s1 = 0.0f, s2 = 0.0f;
    for (int i = 0; i < 1024; ++i) {
        s1 += part1[i*O + o];
        s2 += part2[i*O + o];
    }
    float mean = s1 * invCnt;
    float var  = s2 * invCnt - mean*mean;
    float sc = g[o] * rsqrtf(var + 1e-5f);
    d_scale[o] = sc;
    d_shift[o] = b[o] - mean * sc;
}

// ---------------- column stats over BN rows (dec path) ----------------
__global__ void colstats_kernel(const float* __restrict__ X, int O, float invCnt,
                                const float* __restrict__ g, const float* __restrict__ b) {
    int o = blockIdx.x;
    __shared__ float r1[256], r2[256];
    float s1 = 0.0f, s2 = 0.0f;
    for (int r = threadIdx.x; r < BN_TOT; r += 256) {
        float v = X[(size_t)r*O + o];
        s1 += v; s2 += v*v;
    }
    r1[threadIdx.x] = s1; r2[threadIdx.x] = s2;
    __syncthreads();
    for (int s = 128; s > 0; s >>= 1) {
        if (threadIdx.x < s) {
            r1[threadIdx.x] += r1[threadIdx.x + s];
            r2[threadIdx.x] += r2[threadIdx.x + s];
        }
        __syncthreads();
    }
    if (threadIdx.x == 0) {
        float mean = r1[0] * invCnt;
        float var  = r2[0] * invCnt - mean*mean;
        float sc = g[o] * rsqrtf(var + 1e-5f);
        d_scale[o] = sc;
        d_shift[o] = b[o] - mean * sc;
    }
}

// ---------------- finalize: relu(X*scale + shift) ----------------
__global__ void finalize_kernel(const float* __restrict__ X, int stride, int O,
                                float* __restrict__ out, int total) {
    int t = blockIdx.x * blockDim.x + threadIdx.x;
    if (t >= total) return;
    int p = t / O, o = t % O;
    out[t] = fmaxf(fmaf(X[(size_t)p*stride + o], d_scale[o], d_shift[o]), 0.0f);
}

// ---------------- concat [act(256) | low(48)] -> cat(304) ----------------
__global__ void cat_kernel(const float* __restrict__ act, const float* __restrict__ low,
                           float* __restrict__ cat) {
    int t = blockIdx.x * blockDim.x + threadIdx.x;
    if (t >= BN_TOT*304) return;
    int p = t / 304, c = t % 304;
    cat[t] = (c < 256) ? act[(size_t)p*256 + c] : low[(size_t)p*48 + (c - 256)];
}

// ---------------- pooling over N per batch ----------------
__global__ void pool_partial_kernel(const float* __restrict__ fused, float* __restrict__ pool) {
    int b = blockIdx.x, ch = blockIdx.y, o = threadIdx.x;
    int n0 = ch * 256;
    float mx = NEG_INF, sm = 0.0f;
    for (int i = 0; i < 256; ++i) {
        float v = fused[((size_t)(b*NN + n0 + i))*256 + o];
        mx = fmaxf(mx, v);
        sm += v;
    }
    pool[((size_t)(b*16 + ch))*512 + o]       = mx;
    pool[((size_t)(b*16 + ch))*512 + 256 + o] = sm;
}

__global__ void pool_combine_kernel(const float* __restrict__ pool, float* __restrict__ h) {
    int b = blockIdx.x, o = threadIdx.x;
    float mx = NEG_INF, sm = 0.0f;
    for (int c = 0; c < 16; ++c) {
        mx = fmaxf(mx, pool[((size_t)(b*16 + c))*512 + o]);
        sm += pool[((size_t)(b*16 + c))*512 + 256 + o];
    }
    h[b*512 + o]       = mx;
    h[b*512 + 256 + o] = sm * (1.0f / (float)NN);
}

// ---------------- classifier head ----------------
__global__ void head1_kernel(const float* __restrict__ w, const float* __restrict__ h,
                             float* __restrict__ y1) {
    int b = blockIdx.x, o = threadIdx.x;
    float acc = 0.0f;
    for (int c = 0; c < 512; ++c)
        acc = fmaf(w[o*512 + c], h[b*512 + c], acc);
    y1[b*256 + o] = acc;
}

__global__ void headbn_kernel(const float* __restrict__ y1, const float* __restrict__ g,
                              const float* __restrict__ b, float* __restrict__ h2) {
    int o = threadIdx.x;
    float v0 = y1[0*256 + o], v1 = y1[1*256 + o], v2 = y1[2*256 + o], v3 = y1[3*256 + o];
    float m = 0.25f * (v0 + v1 + v2 + v3);
    float q0 = v0 - m, q1 = v1 - m, q2 = v2 - m, q3 = v3 - m;
    float var = 0.25f * (q0*q0 + q1*q1 + q2*q2 + q3*q3);
    float sc = g[o] * rsqrtf(var + 1e-5f);
    float bo = b[o];
    h2[0*256 + o] = fmaxf(q0*sc + bo, 0.0f);
    h2[1*256 + o] = fmaxf(q1*sc + bo, 0.0f);
    h2[2*256 + o] = fmaxf(q2*sc + bo, 0.0f);
    h2[3*256 + o] = fmaxf(q3*sc + bo, 0.0f);
}

__global__ void head2_kernel(const float* __restrict__ w, const float* __restrict__ h2,
                             float* __restrict__ out) {
    int t = threadIdx.x;            // 160 threads
    if (t >= 160) return;
    int b = t / 40, q = t % 40;
    float acc = 0.0f;
    for (int c = 0; c < 256; ++c)
        acc = fmaf(w[q*256 + c], h2[b*256 + c], acc);
    out[b*40 + q] = acc;
}

// ---------------- host driver ----------------
static float* getF(const void* sym) { void* p = nullptr; cudaGetSymbolAddress(&p, sym); return (float*)p; }

static void conv_stage(const float* in, int C,
                       const float* w, const float* gamma, const float* beta,
                       float* outp, int O,
                       float* G, float* WC, const int* IDX, float* P1, float* P2) {
    wprep_kernel<<<(O*C + 255)/256, 256>>>(w, WC, O, C);
    dim3 gg(BN_TOT/TBM, (2*O + TBN - 1)/TBN);
    sgemm_kernel<<<gg, 256>>>(in, WC, G, BN_TOT, 2*O, C);
    edge_kernel<<<1024, O>>>(G, IDX, O, P1, P2);
    reduce_stats_kernel<<<1, O>>>(P1, P2, gamma, beta, O, 1.0f/(float)(BN_TOT*KNN));
    finalize_kernel<<<(BN_TOT*O + 255)/256, 256>>>(G, 2*O, O, outp, BN_TOT*O);
}

extern "C" void kernel_launch(void* const* d_in, const int* in_sizes, int n_in,
                              void* d_out, int out_size) {
    const float* x      = (const float*)d_in[0];
    const float* w1     = (const float*)d_in[2];
    const float* g1     = (const float*)d_in[3];
    const float* b1     = (const float*)d_in[4];
    const float* w2     = (const float*)d_in[5];
    const float* g2     = (const float*)d_in[6];
    const float* b2     = (const float*)d_in[7];
    const float* w3     = (const float*)d_in[8];
    const float* g3     = (const float*)d_in[9];
    const float* b3     = (const float*)d_in[10];
    const float* w4     = (const float*)d_in[11];
    const float* g4     = (const float*)d_in[12];
    const float* b4     = (const float*)d_in[13];
    const float* dec_w  = (const float*)d_in[14];
    const float* dec_g  = (const float*)d_in[15];
    const float* dec_b  = (const float*)d_in[16];
    const float* fus_w  = (const float*)d_in[17];
    const float* cls_w1 = (const float*)d_in[18];
    const float* cls_g  = (const float*)d_in[19];
    const float* cls_b  = (const float*)d_in[20];
    const float* cls_w2 = (const float*)d_in[21];
    float* out = (float*)d_out;

    float* Xt   = getF(d_Xt);
    float* X2   = getF(d_x2);
    float* G    = getF(d_G);
    float* ACTA = getF(d_actA);
    float* ACTB = getF(d_actB);
    float* OUT1 = getF(d_out1);
    float* LOW  = getF(d_low);
    float* CAT  = getF(d_cat);
    float* FUS  = getF(d_fused);
    float* WC   = getF(d_wcat);
    float* P1   = getF(d_part1);
    float* P2   = getF(d_part2);
    float* POOL = getF(d_pool);
    float* H    = getF(d_h);
    float* Y1   = getF(d_y1);
    float* H2   = getF(d_h2);
    void* ip = nullptr; cudaGetSymbolAddress(&ip, d_idx);
    int* IDX = (int*)ip;

    // prep + knn
    prep_kernel<<<(BN_TOT + 255)/256, 256>>>(x, Xt, X2);
    cudaFuncSetAttribute(knn_kernel, cudaFuncAttributeMaxDynamicSharedMemorySize, 4*NN*4);
    knn_kernel<<<dim3(BB, NN/128), 128, 4*NN*4>>>(Xt, X2, IDX);

    // edge convs
    conv_stage(Xt,   3,   w1, g1, b1, OUT1, 64,  G, WC, IDX, P1, P2);
    conv_stage(OUT1, 64,  w2, g2, b2, ACTA, 128, G, WC, IDX, P1, P2);
    conv_stage(ACTA, 128, w3, g3, b3, ACTB, 256, G, WC, IDX, P1, P2);
    conv_stage(ACTB, 256, w4, g4, b4, ACTA, 256, G, WC, IDX, P1, P2);

    // decoder branch: low = relu(bn(dec_w @ out1))
    {
        dim3 gg(BN_TOT/TBM, 1);
        sgemm_kernel<<<gg, 256>>>(OUT1, dec_w, G, BN_TOT, 48, 64);
        colstats_kernel<<<48, 256>>>(G, 48, 1.0f/(float)BN_TOT, dec_g, dec_b);
        finalize_kernel<<<(BN_TOT*48 + 255)/256, 256>>>(G, 48, 48, LOW, BN_TOT*48);
    }

    // fusion
    cat_kernel<<<(BN_TOT*304 + 255)/256, 256>>>(ACTA, LOW, CAT);
    {
        dim3 gg(BN_TOT/TBM, 2);
        sgemm_kernel<<<gg, 256>>>(CAT, fus_w, FUS, BN_TOT, 256, 304);
    }

    // pool + head
    pool_partial_kernel<<<dim3(4, 16), 256>>>(FUS, POOL);
    pool_combine_kernel<<<4, 256>>>(POOL, H);
    head1_kernel<<<4, 256>>>(cls_w1, H, Y1);
    headbn_kernel<<<1, 256>>>(Y1, cls_g, cls_b, H2);
    head2_kernel<<<1, 160>>>(cls_w2, H2, out);
}

// round 3
// speedup vs baseline: 1.0774x; 1.0774x over previous
#include <cuda_runtime.h>
#include <cstdint>

#define BB 4
#define NN 4096
#define KNN 9
#define BN_TOT (BB*NN)
#define NEG_INF (-3.402823466e38f)

// ---------------- device scratch (static globals; no allocation) ----------------
__device__ float d_Xt[BN_TOT*3];
__device__ float d_x2[BN_TOT];
__device__ int   d_idx[BN_TOT*KNN];
__device__ float d_G[BN_TOT*512];       // GEMM out: per row [U(0..O-1) | Z(O..2O-1)]
__device__ float d_actA[BN_TOT*256];
__device__ float d_actB[BN_TOT*256];
__device__ float d_out1[BN_TOT*64];
__device__ float d_low[BN_TOT*48];
__device__ float d_cat[BN_TOT*304];
__device__ float d_fused[BN_TOT*256];
__device__ float d_wcat[1024*512];      // [Wa-Wb ; Wb] stacked (2O x C)
__device__ float d_part1[1024*256];
__device__ float d_part2[1024*256];
__device__ float d_scale[256];
__device__ float d_shift[256];
__device__ float d_pool[4*16*512];
__device__ float d_h[4*512];
__device__ float d_y1[4*256];
__device__ float d_h2[4*256];

// ---------------- helpers ----------------
__device__ __forceinline__ float tf32_rna(float x) {
    uint32_t u; asm("cvt.rna.tf32.f32 %0, %1;" : "=r"(u) : "f"(x));
    return __uint_as_float(u);
}
__device__ __forceinline__ void mma8(float* d, uint32_t a0, uint32_t a1, uint32_t a2, uint32_t a3,
                                     uint32_t b0, uint32_t b1) {
    asm volatile(
        "mma.sync.aligned.m16n8k8.row.col.f32.tf32.tf32.f32 "
        "{%0,%1,%2,%3},{%4,%5,%6,%7},{%8,%9},{%0,%1,%2,%3};"
        : "+f"(d[0]), "+f"(d[1]), "+f"(d[2]), "+f"(d[3])
        : "r"(a0), "r"(a1), "r"(a2), "r"(a3), "r"(b0), "r"(b1));
}

// ---------------- prep: transpose x to (p,3) + squared norms ----------------
__global__ void prep_kernel(const float* __restrict__ x, float* __restrict__ Xt,
                            float* __restrict__ x2) {
    int t = blockIdx.x * blockDim.x + threadIdx.x;
    if (t >= BN_TOT) return;
    int b = t / NN, n = t % NN;
    float a0 = x[(b*3+0)*NN + n];
    float a1 = x[(b*3+1)*NN + n];
    float a2 = x[(b*3+2)*NN + n];
    Xt[t*3+0] = a0; Xt[t*3+1] = a1; Xt[t*3+2] = a2;
    x2[t] = a0*a0 + a1*a1 + a2*a2;
}

// ---------------- knn ----------------
__global__ void knn_kernel(const float* __restrict__ Xt, const float* __restrict__ x2,
                           int* __restrict__ idxOut) {
    extern __shared__ float sm[];
    float* sx = sm;
    float* sy = sm + NN;
    float* sz = sm + 2*NN;
    float* s2 = sm + 3*NN;
    int b = blockIdx.x;
    int n = blockIdx.y * blockDim.x + threadIdx.x;
    const float* Xb = Xt + (size_t)b*NN*3;
    for (int t = threadIdx.x; t < NN; t += blockDim.x) {
        sx[t] = Xb[t*3+0];
        sy[t] = Xb[t*3+1];
        sz[t] = Xb[t*3+2];
        s2[t] = x2[b*NN + t];
    }
    __syncthreads();
    float px = sx[n], py = sy[n], pz = sz[n], p2 = s2[n];
    float bd[KNN]; int bi[KNN];
#pragma unroll
    for (int j = 0; j < KNN; ++j) { bd[j] = 1e30f; bi[j] = 0; }
#pragma unroll 4
    for (int m = 0; m < NN; ++m) {
        float dot = px*sx[m] + py*sy[m] + pz*sz[m];
        float d = p2 + s2[m] - 2.0f*dot;
        if (m == n) d = 1e30f;
        if (d < bd[KNN-1]) {
            float vd = d; int vi = m;
#pragma unroll
            for (int j = 0; j < KNN; ++j) {
                if (vd < bd[j]) {
                    float td = bd[j]; bd[j] = vd; vd = td;
                    int   ti = bi[j]; bi[j] = vi; vi = ti;
                }
            }
        }
    }
#pragma unroll
    for (int j = 0; j < KNN; ++j)
        idxOut[(b*NN + n)*KNN + j] = b*NN + bi[j];
}

// ---------------- weight prep: wcat = [Wa - Wb ; Wb]  (w is O x 2C) ----------------
__global__ void wprep_kernel(const float* __restrict__ w, float* __restrict__ wc,
                             int O, int C) {
    int t = blockIdx.x * blockDim.x + threadIdx.x;
    if (t >= O*C) return;
    int o = t / C, c = t % C;
    float wa = w[o*2*C + c];
    float wb = w[o*2*C + C + c];
    wc[o*C + c]       = wa - wb;
    wc[(O+o)*C + c]   = wb;
}

// ---------------- conv1: Kc=3 fused GEMM (Nc = 128) ----------------
__global__ void conv1_kernel(const float* __restrict__ Xt, const float* __restrict__ w1,
                             float* __restrict__ G) {
    int t = blockIdx.x * blockDim.x + threadIdx.x;
    if (t >= BN_TOT*128) return;
    int p = t >> 7, o = t & 127;
    float c0, c1, c2;
    if (o < 64) {
        c0 = w1[o*6+0] - w1[o*6+3];
        c1 = w1[o*6+1] - w1[o*6+4];
        c2 = w1[o*6+2] - w1[o*6+5];
    } else {
        int q = o - 64;
        c0 = w1[q*6+3]; c1 = w1[q*6+4]; c2 = w1[q*6+5];
    }
    G[t] = c0*Xt[p*3+0] + c1*Xt[p*3+1] + c2*Xt[p*3+2];
}

// ---------------- tf32 3x-split tensor-core GEMM ----------------
// C[M x Nc] = A[M x Kc] * W[Nc x Kc]^T.  Requires Kc % 16 == 0, M % 128 == 0.
#define BM 128
#define BN 128
#define BK 16
#define SMS 130                    // smem row stride (k-major): conflict-tuned
#define TSZ (2*BK*SMS)             // per hi/lo array (double-buffered)
#define MMA_SMEM (4*TSZ*4)         // bytes

__global__ __launch_bounds__(256, 1)
void mma_gemm(const float* __restrict__ A, const float* __restrict__ W,
              float* __restrict__ C, int Nc, int Kc) {
    extern __shared__ float smem[];
    float* sAh = smem;
    float* sAl = smem + TSZ;
    float* sBh = smem + 2*TSZ;
    float* sBl = smem + 3*TSZ;

    int tid = threadIdx.x;
    int lane = tid & 31, wid = tid >> 5;
    int wm = wid >> 2, wn = wid & 3;       // 2 x 4 warp grid; warp tile 64 x 32
    int g = lane >> 2, tig = lane & 3;
    int bm = blockIdx.x * BM;
    int bn = blockIdx.y * BN;

    int m0 = tid >> 2;                     // 0..63 (row within half-tile)
    int kq = tid & 3;                      // float4 index within BK

    float d[4][4][4];
#pragma unroll
    for (int i = 0; i < 4; ++i)
#pragma unroll
        for (int j = 0; j < 4; ++j)
#pragma unroll
            for (int q = 0; q < 4; ++q) d[i][j][q] = 0.0f;

    int nIter = Kc / BK;
    float4 ra[2], rb[2];

    // ---- prologue: load + commit iter 0 ----
    {
        int k0 = 0;
#pragma unroll
        for (int i = 0; i < 2; ++i) {
            ra[i] = *(const float4*)&A[(size_t)(bm + m0 + i*64)*Kc + k0 + kq*4];
            int n = bn + m0 + i*64;
            rb[i] = (n < Nc) ? *(const float4*)&W[(size_t)n*Kc + k0 + kq*4]
                             : make_float4(0.f, 0.f, 0.f, 0.f);
        }
#pragma unroll
        for (int i = 0; i < 2; ++i) {
            float av[4] = {ra[i].x, ra[i].y, ra[i].z, ra[i].w};
            float bv[4] = {rb[i].x, rb[i].y, rb[i].z, rb[i].w};
#pragma unroll
            for (int j = 0; j < 4; ++j) {
                int kk = kq*4 + j, mm = m0 + i*64;
                float ah = tf32_rna(av[j]);
                sAh[kk*SMS + mm] = ah;
                sAl[kk*SMS + mm] = tf32_rna(av[j] - ah);
                float bh = tf32_rna(bv[j]);
                sBh[kk*SMS + mm] = bh;
                sBl[kk*SMS + mm] = tf32_rna(bv[j] - bh);
            }
        }
    }
    __syncthreads();

    for (int it = 0; it < nIter; ++it) {
        int buf = it & 1;
        int base = buf * (BK*SMS);
        bool more = (it + 1 < nIter);
        if (more) {
            int k0 = (it + 1) * BK;
#pragma unroll
            for (int i = 0; i < 2; ++i) {
                ra[i] = *(const float4*)&A[(size_t)(bm + m0 + i*64)*Kc + k0 + kq*4];
                int n = bn + m0 + i*64;
                rb[i] = (n < Nc) ? *(const float4*)&W[(size_t)n*Kc + k0 + kq*4]
                                 : make_float4(0.f, 0.f, 0.f, 0.f);
            }
        }

        // ---- compute on buf ----
#pragma unroll
        for (int ks = 0; ks < 2; ++ks) {
            int k1 = base + (ks*8 + tig)*SMS;
            int k2 = base + (ks*8 + tig + 4)*SMS;
            uint32_t ah[4][4], al[4][4], bh[4][2], bl[4][2];
#pragma unroll
            for (int mt = 0; mt < 4; ++mt) {
                int r = wm*64 + mt*16 + g;
                ah[mt][0] = __float_as_uint(sAh[k1 + r]);
                ah[mt][1] = __float_as_uint(sAh[k1 + r + 8]);
                ah[mt][2] = __float_as_uint(sAh[k2 + r]);
                ah[mt][3] = __float_as_uint(sAh[k2 + r + 8]);
                al[mt][0] = __float_as_uint(sAl[k1 + r]);
                al[mt][1] = __float_as_uint(sAl[k1 + r + 8]);
                al[mt][2] = __float_as_uint(sAl[k2 + r]);
                al[mt][3] = __float_as_uint(sAl[k2 + r + 8]);
            }
#pragma unroll
            for (int nt = 0; nt < 4; ++nt) {
                int c = wn*32 + nt*8 + g;
                bh[nt][0] = __float_as_uint(sBh[k1 + c]);
                bh[nt][1] = __float_as_uint(sBh[k2 + c]);
                bl[nt][0] = __float_as_uint(sBl[k1 + c]);
                bl[nt][1] = __float_as_uint(sBl[k2 + c]);
            }
#pragma unroll
            for (int mt = 0; mt < 4; ++mt)
#pragma unroll
                for (int nt = 0; nt < 4; ++nt) {
                    mma8(d[mt][nt], al[mt][0], al[mt][1], al[mt][2], al[mt][3],
                         bh[nt][0], bh[nt][1]);
                    mma8(d[mt][nt], ah[mt][0], ah[mt][1], ah[mt][2], ah[mt][3],
                         bl[nt][0], bl[nt][1]);
                    mma8(d[mt][nt], ah[mt][0], ah[mt][1], ah[mt][2], ah[mt][3],
                         bh[nt][0], bh[nt][1]);
                }
        }

        if (more) {
            int base2 = (buf ^ 1) * (BK*SMS);
#pragma unroll
            for (int i = 0; i < 2; ++i) {
                float av[4] = {ra[i].x, ra[i].y, ra[i].z, ra[i].w};
                float bv[4] = {rb[i].x, rb[i].y, rb[i].z, rb[i].w};
#pragma unroll
                for (int j = 0; j < 4; ++j) {
                    int kk = kq*4 + j, mm = m0 + i*64;
                    float ah2 = tf32_rna(av[j]);
                    sAh[base2 + kk*SMS + mm] = ah2;
                    sAl[base2 + kk*SMS + mm] = tf32_rna(av[j] - ah2);
                    float bh2 = tf32_rna(bv[j]);
                    sBh[base2 + kk*SMS + mm] = bh2;
                    sBl[base2 + kk*SMS + mm] = tf32_rna(bv[j] - bh2);
                }
            }
        }
        __syncthreads();
    }

    // ---- epilogue: store ----
#pragma unroll
    for (int mt = 0; mt < 4; ++mt) {
        int row = bm + wm*64 + mt*16 + g;
#pragma unroll
        for (int nt = 0; nt < 4; ++nt) {
            int col = bn + wn*32 + nt*8 + tig*2;
            if (col < Nc) {
                *(float2*)&C[(size_t)row*Nc + col]     = make_float2(d[mt][nt][0], d[mt][nt][1]);
                *(float2*)&C[(size_t)(row+8)*Nc + col] = make_float2(d[mt][nt][2], d[mt][nt][3]);
            }
        }
    }
}

// ---------------- edge pass ----------------
__global__ void edge_kernel(float* __restrict__ G, const int* __restrict__ idx,
                            int O, float* __restrict__ part1, float* __restrict__ part2) {
    int o = threadIdx.x;
    int blk = blockIdx.x;
    int p0 = blk * 16;
    __shared__ int sidx[16*KNN];
    for (int t = threadIdx.x; t < 16*KNN; t += blockDim.x)
        sidx[t] = idx[p0*KNN + t];
    __syncthreads();
    int S = 2*O;
    float s1 = 0.0f, s2 = 0.0f;
    for (int pp = 0; pp < 16; ++pp) {
        int p = p0 + pp;
        float u = G[(size_t)p*S + o];
        float zmax = NEG_INF;
#pragma unroll
        for (int k = 0; k < KNN; ++k) {
            int j = sidx[pp*KNN + k];
            float z = G[(size_t)j*S + O + o];
            float v = u + z;
            zmax = fmaxf(zmax, z);
            s1 += v;
            s2 += v*v;
        }
        G[(size_t)p*S + o] = u + zmax;
    }
    part1[blk*O + o] = s1;
    part2[blk*O + o] = s2;
}

// ---------------- stats reduce ----------------
__global__ void reduce_stats_kernel(const float* __restrict__ part1,
                                    const float* __restrict__ part2,
                                    const float* __restrict__ g, const float* __restrict__ b,
                                    int O, float invCnt) {
    int o = threadIdx.x;
    float s1 = 0.0f, s2 = 0.0f;
    for (int i = 0; i < 1024; ++i) {
        s1 += part1[i*O + o];
        s2 += part2[i*O + o];
    }
    float mean = s1 * invCnt;
    float var  = s2 * invCnt - mean*mean;
    float sc = g[o] * rsqrtf(var + 1e-5f);
    d_scale[o] = sc;
    d_shift[o] = b[o] - mean * sc;
}

__global__ void colstats_kernel(const float* __restrict__ X, int O, float invCnt,
                                const float* __restrict__ g, const float* __restrict__ b) {
    int o = blockIdx.x;
    __shared__ float r1[256], r2[256];
    float s1 = 0.0f, s2 = 0.0f;
    for (int r = threadIdx.x; r < BN_TOT; r += 256) {
        float v = X[(size_t)r*O + o];
        s1 += v; s2 += v*v;
    }
    r1[threadIdx.x] = s1; r2[threadIdx.x] = s2;
    __syncthreads();
    for (int s = 128; s > 0; s >>= 1) {
        if (threadIdx.x < s) {
            r1[threadIdx.x] += r1[threadIdx.x + s];
            r2[threadIdx.x] += r2[threadIdx.x + s];
        }
        __syncthreads();
    }
    if (threadIdx.x == 0) {
        float mean = r1[0] * invCnt;
        float var  = r2[0] * invCnt - mean*mean;
        float sc = g[o] * rsqrtf(var + 1e-5f);
        d_scale[o] = sc;
        d_shift[o] = b[o] - mean * sc;
    }
}

__global__ void finalize_kernel(const float* __restrict__ X, int stride, int O,
                                float* __restrict__ out, int total) {
    int t = blockIdx.x * blockDim.x + threadIdx.x;
    if (t >= total) return;
    int p = t / O, o = t % O;
    out[t] = fmaxf(fmaf(X[(size_t)p*stride + o], d_scale[o], d_shift[o]), 0.0f);
}

__global__ void cat_kernel(const float* __restrict__ act, const float* __restrict__ low,
                           float* __restrict__ cat) {
    int t = blockIdx.x * blockDim.x + threadIdx.x;
    if (t >= BN_TOT*304) return;
    int p = t / 304, c = t % 304;
    cat[t] = (c < 256) ? act[(size_t)p*256 + c] : low[(size_t)p*48 + (c - 256)];
}

__global__ void pool_partial_kernel(const float* __restrict__ fused, float* __restrict__ pool) {
    int b = blockIdx.x, ch = blockIdx.y, o = threadIdx.x;
    int n0 = ch * 256;
    float mx = NEG_INF, sm = 0.0f;
    for (int i = 0; i < 256; ++i) {
        float v = fused[((size_t)(b*NN + n0 + i))*256 + o];
        mx = fmaxf(mx, v);
        sm += v;
    }
    pool[((size_t)(b*16 + ch))*512 + o]       = mx;
    pool[((size_t)(b*16 + ch))*512 + 256 + o] = sm;
}

__global__ void pool_combine_kernel(const float* __restrict__ pool, float* __restrict__ h) {
    int b = blockIdx.x, o = threadIdx.x;
    float mx = NEG_INF, sm = 0.0f;
    for (int c = 0; c < 16; ++c) {
        mx = fmaxf(mx, pool[((size_t)(b*16 + c))*512 + o]);
        sm += pool[((size_t)(b*16 + c))*512 + 256 + o];
    }
    h[b*512 + o]       = mx;
    h[b*512 + 256 + o] = sm * (1.0f / (float)NN);
}

__global__ void head1_kernel(const float* __restrict__ w, const float* __restrict__ h,
                             float* __restrict__ y1) {
    int b = blockIdx.x, o = threadIdx.x;
    float acc = 0.0f;
    for (int c = 0; c < 512; ++c)
        acc = fmaf(w[o*512 + c], h[b*512 + c], acc);
    y1[b*256 + o] = acc;
}

__global__ void headbn_kernel(const float* __restrict__ y1, const float* __restrict__ g,
                              const float* __restrict__ b, float* __restrict__ h2) {
    int o = threadIdx.x;
    float v0 = y1[0*256 + o], v1 = y1[1*256 + o], v2 = y1[2*256 + o], v3 = y1[3*256 + o];
    float m = 0.25f * (v0 + v1 + v2 + v3);
    float q0 = v0 - m, q1 = v1 - m, q2 = v2 - m, q3 = v3 - m;
    float var = 0.25f * (q0*q0 + q1*q1 + q2*q2 + q3*q3);
    float sc = g[o] * rsqrtf(var + 1e-5f);
    float bo = b[o];
    h2[0*256 + o] = fmaxf(q0*sc + bo, 0.0f);
    h2[1*256 + o] = fmaxf(q1*sc + bo, 0.0f);
    h2[2*256 + o] = fmaxf(q2*sc + bo, 0.0f);
    h2[3*256 + o] = fmaxf(q3*sc + bo, 0.0f);
}

__global__ void head2_kernel(const float* __restrict__ w, const float* __restrict__ h2,
                             float* __restrict__ out) {
    int t = threadIdx.x;
    if (t >= 160) return;
    int b = t / 40, q = t % 40;
    float acc = 0.0f;
    for (int c = 0; c < 256; ++c)
        acc = fmaf(w[q*256 + c], h2[b*256 + c], acc);
    out[b*40 + q] = acc;
}

// ---------------- host driver ----------------
static float* getF(const void* sym) { void* p = nullptr; cudaGetSymbolAddress(&p, sym); return (float*)p; }

static void conv_stage(const float* in, int C,
                       const float* w, const float* gamma, const float* beta,
                       float* outp, int O,
                       float* G, float* WC, const int* IDX, float* P1, float* P2) {
    wprep_kernel<<<(O*C + 255)/256, 256>>>(w, WC, O, C);
    dim3 gg(BN_TOT/BM, (2*O + BN - 1)/BN);
    mma_gemm<<<gg, 256, MMA_SMEM>>>(in, WC, G, 2*O, C);
    edge_kernel<<<1024, O>>>(G, IDX, O, P1, P2);
    reduce_stats_kernel<<<1, O>>>(P1, P2, gamma, beta, O, 1.0f/(float)(BN_TOT*KNN));
    finalize_kernel<<<(BN_TOT*O + 255)/256, 256>>>(G, 2*O, O, outp, BN_TOT*O);
}

extern "C" void kernel_launch(void* const* d_in, const int* in_sizes, int n_in,
                              void* d_out, int out_size) {
    const float* x      = (const float*)d_in[0];
    const float* w1     = (const float*)d_in[2];
    const float* g1     = (const float*)d_in[3];
    const float* b1     = (const float*)d_in[4];
    const float* w2     = (const float*)d_in[5];
    const float* g2     = (const float*)d_in[6];
    const float* b2     = (const float*)d_in[7];
    const float* w3     = (const float*)d_in[8];
    const float* g3     = (const float*)d_in[9];
    const float* b3     = (const float*)d_in[10];
    const float* w4     = (const float*)d_in[11];
    const float* g4     = (const float*)d_in[12];
    const float* b4     = (const float*)d_in[13];
    const float* dec_w  = (const float*)d_in[14];
    const float* dec_g  = (const float*)d_in[15];
    const float* dec_b  = (const float*)d_in[16];
    const float* fus_w  = (const float*)d_in[17];
    const float* cls_w1 = (const float*)d_in[18];
    const float* cls_g  = (const float*)d_in[19];
    const float* cls_b  = (const float*)d_in[20];
    const float* cls_w2 = (const float*)d_in[21];
    float* out = (float*)d_out;

    float* Xt   = getF(d_Xt);
    float* X2   = getF(d_x2);
    float* G    = getF(d_G);
    float* ACTA = getF(d_actA);
    float* ACTB = getF(d_actB);
    float* OUT1 = getF(d_out1);
    float* LOW  = getF(d_low);
    float* CAT  = getF(d_cat);
    float* FUS  = getF(d_fused);
    float* WC   = getF(d_wcat);
    float* P1   = getF(d_part1);
    float* P2   = getF(d_part2);
    float* POOL = getF(d_pool);
    float* H    = getF(d_h);
    float* Y1   = getF(d_y1);
    float* H2   = getF(d_h2);
    void* ip = nullptr; cudaGetSymbolAddress(&ip, d_idx);
    int* IDX = (int*)ip;

    static int attr_done = 0;
    if (!attr_done) {
        cudaFuncSetAttribute(knn_kernel, cudaFuncAttributeMaxDynamicSharedMemorySize, 4*NN*4);
        cudaFuncSetAttribute(mma_gemm, cudaFuncAttributeMaxDynamicSharedMemorySize, MMA_SMEM);
        attr_done = 1;
    }

    // prep + knn
    prep_kernel<<<(BN_TOT + 255)/256, 256>>>(x, Xt, X2);
    knn_kernel<<<dim3(BB, NN/128), 128, 4*NN*4>>>(Xt, X2, IDX);

    // conv1 (Kc=3: fused elementwise GEMM)
    conv1_kernel<<<(BN_TOT*128 + 255)/256, 256>>>(Xt, w1, G);
    edge_kernel<<<1024, 64>>>(G, IDX, 64, P1, P2);
    reduce_stats_kernel<<<1, 64>>>(P1, P2, g1, b1, 64, 1.0f/(float)(BN_TOT*KNN));
    finalize_kernel<<<(BN_TOT*64 + 255)/256, 256>>>(G, 128, 64, OUT1, BN_TOT*64);

    // conv2..4
    conv_stage(OUT1, 64,  w2, g2, b2, ACTA, 128, G, WC, IDX, P1, P2);
    conv_stage(ACTA, 128, w3, g3, b3, ACTB, 256, G, WC, IDX, P1, P2);
    conv_stage(ACTB, 256, w4, g4, b4, ACTA, 256, G, WC, IDX, P1, P2);

    // decoder branch: low = relu(bn(dec_w @ out1))
    {
        dim3 gg(BN_TOT/BM, 1);
        mma_gemm<<<gg, 256, MMA_SMEM>>>(OUT1, dec_w, G, 48, 64);
        colstats_kernel<<<48, 256>>>(G, 48, 1.0f/(float)BN_TOT, dec_g, dec_b);
        finalize_kernel<<<(BN_TOT*48 + 255)/256, 256>>>(G, 48, 48, LOW, BN_TOT*48);
    }

    // fusion
    cat_kernel<<<(BN_TOT*304 + 255)/256, 256>>>(ACTA, LOW, CAT);
    {
        dim3 gg(BN_TOT/BM, 2);
        mma_gemm<<<gg, 256, MMA_SMEM>>>(CAT, fus_w, FUS, 256, 304);
    }

    // pool + head
    pool_partial_kernel<<<dim3(4, 16), 256>>>(FUS, POOL);
    pool_combine_kernel<<<4, 256>>>(POOL, H);
    head1_kernel<<<4, 256>>>(cls_w1, H, Y1);
    headbn_kernel<<<1, 256>>>(Y1, cls_g, cls_b, H2);
    head2_kernel<<<1, 160>>>(cls_w2, H2, out);
}

// round 4
// speedup vs baseline: 1.3892x; 1.2893x over previous
#include <cuda_runtime.h>
#include <cstdint>

#define BB 4
#define NN 4096
#define KNN 9
#define KS 4                      // knn split chunks
#define CHUNK (NN/KS)
#define BN_TOT (BB*NN)
#define NEG_INF (-3.402823466e38f)

// ---------------- device scratch ----------------
__device__ float d_Xt[BN_TOT*3];
__device__ float d_x2[BN_TOT];
__device__ int   d_idx[BN_TOT*KNN];
__device__ float d_candD[BN_TOT*KS*KNN];
__device__ int   d_candI[BN_TOT*KS*KNN];
__device__ float d_G1[BN_TOT*128];
__device__ float d_G2[BN_TOT*256];
__device__ float d_G3[BN_TOT*512];
__device__ float d_G4[BN_TOT*512];
__device__ float d_Gdec[BN_TOT*48];
__device__ float d_cat[BN_TOT*304];
__device__ float d_fused[BN_TOT*256];
__device__ float d_part1[1024*256];
__device__ float d_part2[1024*256];
__device__ __align__(16) float d_scaleA[5][256];
__device__ __align__(16) float d_shiftA[5][256];
__device__ float d_pool[4*16*512];
__device__ float d_h[4*512];
__device__ float d_y1[4*256];
__device__ float d_h2[4*256];

// ---------------- helpers ----------------
__device__ __forceinline__ float tf32_rna(float x) {
    uint32_t u; asm("cvt.rna.tf32.f32 %0, %1;" : "=r"(u) : "f"(x));
    return __uint_as_float(u);
}
__device__ __forceinline__ void mma8(float* d, uint32_t a0, uint32_t a1, uint32_t a2, uint32_t a3,
                                     uint32_t b0, uint32_t b1) {
    asm volatile(
        "mma.sync.aligned.m16n8k8.row.col.f32.tf32.tf32.f32 "
        "{%0,%1,%2,%3},{%4,%5,%6,%7},{%8,%9},{%0,%1,%2,%3};"
        : "+f"(d[0]), "+f"(d[1]), "+f"(d[2]), "+f"(d[3])
        : "r"(a0), "r"(a1), "r"(a2), "r"(a3), "r"(b0), "r"(b1));
}

// ---------------- prep ----------------
__global__ void prep_kernel(const float* __restrict__ x, float* __restrict__ Xt,
                            float* __restrict__ x2) {
    int t = blockIdx.x * blockDim.x + threadIdx.x;
    if (t >= BN_TOT) return;
    int b = t / NN, n = t % NN;
    float a0 = x[(b*3+0)*NN + n];
    float a1 = x[(b*3+1)*NN + n];
    float a2 = x[(b*3+2)*NN + n];
    Xt[t*3+0] = a0; Xt[t*3+1] = a1; Xt[t*3+2] = a2;
    x2[t] = a0*a0 + a1*a1 + a2*a2;
}

// ---------------- knn: chunked partial top-9 ----------------
__global__ void knn_part_kernel(const float* __restrict__ Xt, const float* __restrict__ x2,
                                float* __restrict__ candD, int* __restrict__ candI) {
    __shared__ float sx[CHUNK], sy[CHUNK], sz[CHUNK], s2[CHUNK];
    int b  = blockIdx.x;
    int n  = blockIdx.y * blockDim.x + threadIdx.x;
    int cs = blockIdx.z;
    int m0 = cs * CHUNK;
    const float* Xb = Xt + (size_t)b*NN*3;
    for (int t = threadIdx.x; t < CHUNK; t += blockDim.x) {
        int m = m0 + t;
        sx[t] = Xb[m*3+0];
        sy[t] = Xb[m*3+1];
        sz[t] = Xb[m*3+2];
        s2[t] = x2[b*NN + m];
    }
    __syncthreads();
    float px = Xb[n*3+0], py = Xb[n*3+1], pz = Xb[n*3+2], p2 = x2[b*NN + n];
    float bd[KNN]; int bi[KNN];
#pragma unroll
    for (int j = 0; j < KNN; ++j) { bd[j] = 1e30f; bi[j] = 0; }
#pragma unroll 4
    for (int mm = 0; mm < CHUNK; ++mm) {
        float dot = px*sx[mm] + py*sy[mm] + pz*sz[mm];
        float d = p2 + s2[mm] - 2.0f*dot;
        int m = m0 + mm;
        if (m == n) d = 1e30f;
        if (d < bd[KNN-1]) {
            float vd = d; int vi = m;
#pragma unroll
            for (int j = 0; j < KNN; ++j) {
                if (vd < bd[j]) {
                    float td = bd[j]; bd[j] = vd; vd = td;
                    int   ti = bi[j]; bi[j] = vi; vi = ti;
                }
            }
        }
    }
    size_t base = ((size_t)(b*NN + n)*KS + cs)*KNN;
#pragma unroll
    for (int j = 0; j < KNN; ++j) {
        candD[base + j] = bd[j];
        candI[base + j] = bi[j];
    }
}

__global__ void knn_merge_kernel(const float* __restrict__ candD, const int* __restrict__ candI,
                                 int* __restrict__ idxOut) {
    int t = blockIdx.x * blockDim.x + threadIdx.x;
    if (t >= BN_TOT) return;
    int b = t / NN;
    float bd[KNN]; int bi[KNN];
#pragma unroll
    for (int j = 0; j < KNN; ++j) { bd[j] = 1e30f; bi[j] = 0; }
    size_t base = (size_t)t*KS*KNN;
    for (int c = 0; c < KS*KNN; ++c) {
        float d = candD[base + c];
        int   m = candI[base + c];
        if (d < bd[KNN-1]) {
            float vd = d; int vi = m;
#pragma unroll
            for (int j = 0; j < KNN; ++j) {
                if (vd < bd[j]) {
                    float td = bd[j]; bd[j] = vd; vd = td;
                    int   ti = bi[j]; bi[j] = vi; vi = ti;
                }
            }
        }
    }
#pragma unroll
    for (int j = 0; j < KNN; ++j)
        idxOut[t*KNN + j] = b*NN + bi[j];
}

// ---------------- conv1: Kc=3 fused GEMM (Nc = 128) ----------------
__global__ void conv1_kernel(const float* __restrict__ Xt, const float* __restrict__ w1,
                             float* __restrict__ G) {
    __shared__ float cw0[128], cw1[128], cw2[128];
    int tid = threadIdx.x;
    if (tid < 128) {
        if (tid < 64) {
            cw0[tid] = w1[tid*6+0] - w1[tid*6+3];
            cw1[tid] = w1[tid*6+1] - w1[tid*6+4];
            cw2[tid] = w1[tid*6+2] - w1[tid*6+5];
        } else {
            int q = tid - 64;
            cw0[tid] = w1[q*6+3]; cw1[tid] = w1[q*6+4]; cw2[tid] = w1[q*6+5];
        }
    }
    __syncthreads();
    int base = blockIdx.x * 4096;
    for (int e = tid; e < 4096; e += 256) {
        int t = base + e;
        int p = t >> 7, o = t & 127;
        G[t] = cw0[o]*Xt[p*3+0] + cw1[o]*Xt[p*3+1] + cw2[o]*Xt[p*3+2];
    }
}

// ---------------- tf32 3x-split tensor-core GEMM ----------------
// C[M x Nc] = Aeff[M x Kc] * Weff[Nc x Kc]^T
// Aeff = (scaleStage>=0) ? relu(A*scale+shift) : A      (per-channel k affine)
// Weff = (wmode==1) ? [Wa-Wb ; Wb] from raw w (O x 2Kc) : W (Nc x Kc)
#define BM 128
#define BN 128
#define BK 16
#define SMS 130
#define TSZ (2*BK*SMS)
#define MMA_SMEM (4*TSZ*4)

__global__ __launch_bounds__(256, 1)
void mma_gemm(const float* __restrict__ A, int lda,
              const float* __restrict__ W, int wmode, int O,
              float* __restrict__ C, int Nc, int Kc, int scaleStage) {
    extern __shared__ float smem[];
    float* sAh = smem;
    float* sAl = smem + TSZ;
    float* sBh = smem + 2*TSZ;
    float* sBl = smem + 3*TSZ;

    int tid = threadIdx.x;
    int lane = tid & 31, wid = tid >> 5;
    int wm = wid >> 2, wn = wid & 3;
    int g = lane >> 2, tig = lane & 3;
    int bm = blockIdx.x * BM;
    int bn = blockIdx.y * BN;

    int m0 = tid >> 2;
    int kq = tid & 3;

    float d[4][4][4];
#pragma unroll
    for (int i = 0; i < 4; ++i)
#pragma unroll
        for (int j = 0; j < 4; ++j)
#pragma unroll
            for (int q = 0; q < 4; ++q) d[i][j][q] = 0.0f;

    int nIter = Kc / BK;
    float4 ra[2], rb[2];

    const float* scp = (scaleStage >= 0) ? d_scaleA[scaleStage] : nullptr;
    const float* shp = (scaleStage >= 0) ? d_shiftA[scaleStage] : nullptr;

    // loader lambda-ish via macro
#define LOAD_TILE(K0)                                                            \
    {                                                                            \
        int k0_ = (K0);                                                          \
        float4 sc4, sh4;                                                         \
        if (scp) {                                                               \
            sc4 = *(const float4*)&scp[k0_ + kq*4];                              \
            sh4 = *(const float4*)&shp[k0_ + kq*4];                              \
        }                                                                        \
        _Pragma("unroll")                                                        \
        for (int i = 0; i < 2; ++i) {                                            \
            ra[i] = *(const float4*)&A[(size_t)(bm + m0 + i*64)*lda + k0_ + kq*4];\
            if (scp) {                                                           \
                ra[i].x = fmaxf(fmaf(ra[i].x, sc4.x, sh4.x), 0.0f);              \
                ra[i].y = fmaxf(fmaf(ra[i].y, sc4.y, sh4.y), 0.0f);              \
                ra[i].z = fmaxf(fmaf(ra[i].z, sc4.z, sh4.z), 0.0f);              \
                ra[i].w = fmaxf(fmaf(ra[i].w, sc4.w, sh4.w), 0.0f);              \
            }                                                                    \
            int n = bn + m0 + i*64;                                              \
            if (wmode == 1) {                                                    \
                if (n < O) {                                                     \
                    float4 wa = *(const float4*)&W[(size_t)n*2*Kc + k0_ + kq*4]; \
                    float4 wb = *(const float4*)&W[(size_t)n*2*Kc + Kc + k0_ + kq*4];\
                    rb[i] = make_float4(wa.x-wb.x, wa.y-wb.y, wa.z-wb.z, wa.w-wb.w);\
                } else {                                                         \
                    rb[i] = *(const float4*)&W[(size_t)(n-O)*2*Kc + Kc + k0_ + kq*4];\
                }                                                                \
            } else {                                                             \
                rb[i] = (n < Nc) ? *(const float4*)&W[(size_t)n*Kc + k0_ + kq*4] \
                                 : make_float4(0.f, 0.f, 0.f, 0.f);              \
            }                                                                    \
        }                                                                        \
    }

#define COMMIT_TILE(BASE)                                                        \
    {                                                                            \
        int base_ = (BASE);                                                      \
        _Pragma("unroll")                                                        \
        for (int i = 0; i < 2; ++i) {                                            \
            float av[4] = {ra[i].x, ra[i].y, ra[i].z, ra[i].w};                  \
            float bv[4] = {rb[i].x, rb[i].y, rb[i].z, rb[i].w};                  \
            _Pragma("unroll")                                                    \
            for (int j = 0; j < 4; ++j) {                                        \
                int kk = kq*4 + j, mm = m0 + i*64;                               \
                float ah = tf32_rna(av[j]);                                      \
                sAh[base_ + kk*SMS + mm] = ah;                                   \
                sAl[base_ + kk*SMS + mm] = tf32_rna(av[j] - ah);                 \
                float bh = tf32_rna(bv[j]);                                      \
                sBh[base_ + kk*SMS + mm] = bh;                                   \
                sBl[base_ + kk*SMS + mm] = tf32_rna(bv[j] - bh);                 \
            }                                                                    \
        }                                                                        \
    }

    LOAD_TILE(0)
    COMMIT_TILE(0)
    __syncthreads();

    for (int it = 0; it < nIter; ++it) {
        int buf = it & 1;
        int base = buf * (BK*SMS);
        bool more = (it + 1 < nIter);
        if (more) LOAD_TILE((it + 1) * BK)

#pragma unroll
        for (int ks = 0; ks < 2; ++ks) {
            int k1 = base + (ks*8 + tig)*SMS;
            int k2 = base + (ks*8 + tig + 4)*SMS;
            uint32_t ah[4][4], al[4][4], bh[4][2], bl[4][2];
#pragma unroll
            for (int mt = 0; mt < 4; ++mt) {
                int r = wm*64 + mt*16 + g;
                ah[mt][0] = __float_as_uint(sAh[k1 + r]);
                ah[mt][1] = __float_as_uint(sAh[k1 + r + 8]);
                ah[mt][2] = __float_as_uint(sAh[k2 + r]);
                ah[mt][3] = __float_as_uint(sAh[k2 + r + 8]);
                al[mt][0] = __float_as_uint(sAl[k1 + r]);
                al[mt][1] = __float_as_uint(sAl[k1 + r + 8]);
                al[mt][2] = __float_as_uint(sAl[k2 + r]);
                al[mt][3] = __float_as_uint(sAl[k2 + r + 8]);
            }
#pragma unroll
            for (int nt = 0; nt < 4; ++nt) {
                int c = wn*32 + nt*8 + g;
                bh[nt][0] = __float_as_uint(sBh[k1 + c]);
                bh[nt][1] = __float_as_uint(sBh[k2 + c]);
                bl[nt][0] = __float_as_uint(sBl[k1 + c]);
                bl[nt][1] = __float_as_uint(sBl[k2 + c]);
            }
#pragma unroll
            for (int mt = 0; mt < 4; ++mt)
#pragma unroll
                for (int nt = 0; nt < 4; ++nt) {
                    mma8(d[mt][nt], al[mt][0], al[mt][1], al[mt][2], al[mt][3],
                         bh[nt][0], bh[nt][1]);
                    mma8(d[mt][nt], ah[mt][0], ah[mt][1], ah[mt][2], ah[mt][3],
                         bl[nt][0], bl[nt][1]);
                    mma8(d[mt][nt], ah[mt][0], ah[mt][1], ah[mt][2], ah[mt][3],
                         bh[nt][0], bh[nt][1]);
                }
        }

        if (more) COMMIT_TILE((buf ^ 1) * (BK*SMS))
        __syncthreads();
    }

#pragma unroll
    for (int mt = 0; mt < 4; ++mt) {
        int row = bm + wm*64 + mt*16 + g;
#pragma unroll
        for (int nt = 0; nt < 4; ++nt) {
            int col = bn + wn*32 + nt*8 + tig*2;
            if (col < Nc) {
                *(float2*)&C[(size_t)row*Nc + col]     = make_float2(d[mt][nt][0], d[mt][nt][1]);
                *(float2*)&C[(size_t)(row+8)*Nc + col] = make_float2(d[mt][nt][2], d[mt][nt][3]);
            }
        }
    }
#undef LOAD_TILE
#undef COMMIT_TILE
}

// ---------------- edge pass: 256 threads, points x channels packing ----------------
__global__ void edge_kernel(float* __restrict__ G, const int* __restrict__ idx,
                            int O, float* __restrict__ part1, float* __restrict__ part2) {
    int tid = threadIdx.x;
    int o = tid % O;          // O in {64,128,256}
    int pr = tid / O;
    int R = 256 / O;
    int blk = blockIdx.x;
    int p0 = blk * 16;
    __shared__ int sidx[16*KNN];
    for (int t = tid; t < 16*KNN; t += 256)
        sidx[t] = idx[p0*KNN + t];
    __syncthreads();
    int S = 2*O;
    float s1 = 0.0f, s2 = 0.0f;
    for (int pp = pr; pp < 16; pp += R) {
        int p = p0 + pp;
        float u = G[(size_t)p*S + o];
        float zmax = NEG_INF;
#pragma unroll
        for (int k = 0; k < KNN; ++k) {
            int j = sidx[pp*KNN + k];
            float z = G[(size_t)j*S + O + o];
            float v = u + z;
            zmax = fmaxf(zmax, z);
            s1 += v;
            s2 += v*v;
        }
        G[(size_t)p*S + o] = u + zmax;
    }
    __shared__ float red1[256], red2[256];
    red1[tid] = s1; red2[tid] = s2;
    __syncthreads();
    for (int r = R >> 1; r > 0; r >>= 1) {
        if (pr < r) {
            red1[tid] += red1[tid + r*O];
            red2[tid] += red2[tid + r*O];
        }
        __syncthreads();
    }
    if (pr == 0) {
        part1[blk*O + o] = red1[tid];
        part2[blk*O + o] = red2[tid];
    }
}

// ---------------- parallel stats reduce: one block per channel ----------------
__global__ void reduce_stats_kernel(const float* __restrict__ part1,
                                    const float* __restrict__ part2,
                                    const float* __restrict__ g, const float* __restrict__ b,
                                    int O, float invCnt, int stage) {
    int o = blockIdx.x;
    int tid = threadIdx.x;
    float s1 = 0.0f, s2 = 0.0f;
    for (int i = tid; i < 1024; i += 256) {
        s1 += part1[(size_t)i*O + o];
        s2 += part2[(size_t)i*O + o];
    }
    __shared__ float r1[256], r2[256];
    r1[tid] = s1; r2[tid] = s2;
    __syncthreads();
    for (int s = 128; s > 0; s >>= 1) {
        if (tid < s) { r1[tid] += r1[tid + s]; r2[tid] += r2[tid + s]; }
        __syncthreads();
    }
    if (tid == 0) {
        float mean = r1[0] * invCnt;
        float var  = r2[0] * invCnt - mean*mean;
        float sc = g[o] * rsqrtf(var + 1e-5f);
        d_scaleA[stage][o] = sc;
        d_shiftA[stage][o] = b[o] - mean * sc;
    }
}

// ---------------- column stats over BN rows (dec path) ----------------
__global__ void colstats_kernel(const float* __restrict__ X, int O, float invCnt,
                                const float* __restrict__ g, const float* __restrict__ b,
                                int stage) {
    int o = blockIdx.x;
    __shared__ float r1[256], r2[256];
    float s1 = 0.0f, s2 = 0.0f;
    for (int r = threadIdx.x; r < BN_TOT; r += 256) {
        float v = X[(size_t)r*O + o];
        s1 += v; s2 += v*v;
    }
    r1[threadIdx.x] = s1; r2[threadIdx.x] = s2;
    __syncthreads();
    for (int s = 128; s > 0; s >>= 1) {
        if (threadIdx.x < s) {
            r1[threadIdx.x] += r1[threadIdx.x + s];
            r2[threadIdx.x] += r2[threadIdx.x + s];
        }
        __syncthreads();
    }
    if (threadIdx.x == 0) {
        float mean = r1[0] * invCnt;
        float var  = r2[0] * invCnt - mean*mean;
        float sc = g[o] * rsqrtf(var + 1e-5f);
        d_scaleA[stage][o] = sc;
        d_shiftA[stage][o] = b[o] - mean * sc;
    }
}

// ---------------- cat with fused affines: [relu(aff3(G4)) | relu(aff4(Gdec))] ----------------
__global__ void cat_kernel(const float* __restrict__ G4, const float* __restrict__ Gdec,
                           float* __restrict__ cat) {
    int t = blockIdx.x * blockDim.x + threadIdx.x;
    if (t >= BN_TOT*304) return;
    int p = t / 304, c = t % 304;
    float v;
    if (c < 256)
        v = fmaxf(fmaf(G4[(size_t)p*512 + c], d_scaleA[3][c], d_shiftA[3][c]), 0.0f);
    else {
        int q = c - 256;
        v = fmaxf(fmaf(Gdec[(size_t)p*48 + q], d_scaleA[4][q], d_shiftA[4][q]), 0.0f);
    }
    cat[t] = v;
}

// ---------------- pooling ----------------
__global__ void pool_partial_kernel(const float* __restrict__ fused, float* __restrict__ pool) {
    int b = blockIdx.x, ch = blockIdx.y, o = threadIdx.x;
    int n0 = ch * 256;
    float mx = NEG_INF, sm = 0.0f;
    for (int i = 0; i < 256; ++i) {
        float v = fused[((size_t)(b*NN + n0 + i))*256 + o];
        mx = fmaxf(mx, v);
        sm += v;
    }
    pool[((size_t)(b*16 + ch))*512 + o]       = mx;
    pool[((size_t)(b*16 + ch))*512 + 256 + o] = sm;
}

__global__ void pool_combine_kernel(const float* __restrict__ pool, float* __restrict__ h) {
    int b = blockIdx.x, o = threadIdx.x;
    float mx = NEG_INF, sm = 0.0f;
    for (int c = 0; c < 16; ++c) {
        mx = fmaxf(mx, pool[((size_t)(b*16 + c))*512 + o]);
        sm += pool[((size_t)(b*16 + c))*512 + 256 + o];
    }
    h[b*512 + o]       = mx;
    h[b*512 + 256 + o] = sm * (1.0f / (float)NN);
}

// ---------------- classifier head ----------------
__global__ void head1_kernel(const float* __restrict__ w, const float* __restrict__ h,
                             float* __restrict__ y1) {
    int b = blockIdx.x, o = threadIdx.x;
    float acc = 0.0f;
    for (int c = 0; c < 512; ++c)
        acc = fmaf(w[o*512 + c], h[b*512 + c], acc);
    y1[b*256 + o] = acc;
}

__global__ void headbn_kernel(const float* __restrict__ y1, const float* __restrict__ g,
                              const float* __restrict__ b, float* __restrict__ h2) {
    int o = threadIdx.x;
    float v0 = y1[0*256 + o], v1 = y1[1*256 + o], v2 = y1[2*256 + o], v3 = y1[3*256 + o];
    float m = 0.25f * (v0 + v1 + v2 + v3);
    float q0 = v0 - m, q1 = v1 - m, q2 = v2 - m, q3 = v3 - m;
    float var = 0.25f * (q0*q0 + q1*q1 + q2*q2 + q3*q3);
    float sc = g[o] * rsqrtf(var + 1e-5f);
    float bo = b[o];
    h2[0*256 + o] = fmaxf(q0*sc + bo, 0.0f);
    h2[1*256 + o] = fmaxf(q1*sc + bo, 0.0f);
    h2[2*256 + o] = fmaxf(q2*sc + bo, 0.0f);
    h2[3*256 + o] = fmaxf(q3*sc + bo, 0.0f);
}

__global__ void head2_kernel(const float* __restrict__ w, const float* __restrict__ h2,
                             float* __restrict__ out) {
    int t = threadIdx.x;
    if (t >= 160) return;
    int b = t / 40, q = t % 40;
    float acc = 0.0f;
    for (int c = 0; c < 256; ++c)
        acc = fmaf(w[q*256 + c], h2[b*256 + c], acc);
    out[b*40 + q] = acc;
}

// ---------------- host driver ----------------
static float* getF(const void* sym) { void* p = nullptr; cudaGetSymbolAddress(&p, sym); return (float*)p; }

extern "C" void kernel_launch(void* const* d_in, const int* in_sizes, int n_in,
                              void* d_out, int out_size) {
    const float* x      = (const float*)d_in[0];
    const float* w1     = (const float*)d_in[2];
    const float* g1     = (const float*)d_in[3];
    const float* b1     = (const float*)d_in[4];
    const float* w2     = (const float*)d_in[5];
    const float* g2     = (const float*)d_in[6];
    const float* b2     = (const float*)d_in[7];
    const float* w3     = (const float*)d_in[8];
    const float* g3     = (const float*)d_in[9];
    const float* b3     = (const float*)d_in[10];
    const float* w4     = (const float*)d_in[11];
    const float* g4     = (const float*)d_in[12];
    const float* b4     = (const float*)d_in[13];
    const float* dec_w  = (const float*)d_in[14];
    const float* dec_g  = (const float*)d_in[15];
    const float* dec_b  = (const float*)d_in[16];
    const float* fus_w  = (const float*)d_in[17];
    const float* cls_w1 = (const float*)d_in[18];
    const float* cls_g  = (const float*)d_in[19];
    const float* cls_b  = (const float*)d_in[20];
    const float* cls_w2 = (const float*)d_in[21];
    float* out = (float*)d_out;

    float* Xt   = getF(d_Xt);
    float* X2   = getF(d_x2);
    float* CD   = getF(d_candD);
    float* G1   = getF(d_G1);
    float* G2   = getF(d_G2);
    float* G3   = getF(d_G3);
    float* G4   = getF(d_G4);
    float* GD   = getF(d_Gdec);
    float* CAT  = getF(d_cat);
    float* FUS  = getF(d_fused);
    float* P1   = getF(d_part1);
    float* P2   = getF(d_part2);
    float* POOL = getF(d_pool);
    float* H    = getF(d_h);
    float* Y1   = getF(d_y1);
    float* H2   = getF(d_h2);
    void* ip = nullptr; cudaGetSymbolAddress(&ip, d_idx);
    int* IDX = (int*)ip;
    void* cp = nullptr; cudaGetSymbolAddress(&cp, d_candI);
    int* CI = (int*)cp;

    static int attr_done = 0;
    if (!attr_done) {
        cudaFuncSetAttribute(mma_gemm, cudaFuncAttributeMaxDynamicSharedMemorySize, MMA_SMEM);
        attr_done = 1;
    }

    // prep + knn (chunked)
    prep_kernel<<<(BN_TOT + 255)/256, 256>>>(x, Xt, X2);
    knn_part_kernel<<<dim3(BB, NN/128, KS), 128>>>(Xt, X2, CD, CI);
    knn_merge_kernel<<<(BN_TOT + 255)/256, 256>>>(CD, CI, IDX);

    // conv1 (Kc=3 special)
    conv1_kernel<<<BN_TOT*128/4096, 256>>>(Xt, w1, G1);
    edge_kernel<<<1024, 256>>>(G1, IDX, 64, P1, P2);
    reduce_stats_kernel<<<64, 256>>>(P1, P2, g1, b1, 64, 1.0f/(float)(BN_TOT*KNN), 0);

    // conv2: A = relu(aff0(G1[:, :64])), W folded from w2 (128 x 128)
    mma_gemm<<<dim3(BN_TOT/BM, 2), 256, MMA_SMEM>>>(G1, 128, w2, 1, 128, G2, 256, 64, 0);
    edge_kernel<<<1024, 256>>>(G2, IDX, 128, P1, P2);
    reduce_stats_kernel<<<128, 256>>>(P1, P2, g2, b2, 128, 1.0f/(float)(BN_TOT*KNN), 1);

    // conv3
    mma_gemm<<<dim3(BN_TOT/BM, 4), 256, MMA_SMEM>>>(G2, 256, w3, 1, 256, G3, 512, 128, 1);
    edge_kernel<<<1024, 256>>>(G3, IDX, 256, P1, P2);
    reduce_stats_kernel<<<256, 256>>>(P1, P2, g3, b3, 256, 1.0f/(float)(BN_TOT*KNN), 2);

    // conv4
    mma_gemm<<<dim3(BN_TOT/BM, 4), 256, MMA_SMEM>>>(G3, 512, w4, 1, 256, G4, 512, 256, 2);
    edge_kernel<<<1024, 256>>>(G4, IDX, 256, P1, P2);
    reduce_stats_kernel<<<256, 256>>>(P1, P2, g4, b4, 256, 1.0f/(float)(BN_TOT*KNN), 3);

    // decoder: Gdec = relu(aff0(G1[:, :64])) @ dec_w^T
    mma_gemm<<<dim3(BN_TOT/BM, 1), 256, MMA_SMEM>>>(G1, 128, dec_w, 0, 0, GD, 48, 64, 0);
    colstats_kernel<<<48, 256>>>(GD, 48, 1.0f/(float)BN_TOT, dec_g, dec_b, 4);

    // fused concat (applies aff3 on G4 part, aff4 on dec part)
    cat_kernel<<<(BN_TOT*304 + 255)/256, 256>>>(G4, GD, CAT);
    mma_gemm<<<dim3(BN_TOT/BM, 2), 256, MMA_SMEM>>>(CAT, 304, fus_w, 0, 0, FUS, 256, 304, -1);

    // pool + head
    pool_partial_kernel<<<dim3(4, 16), 256>>>(FUS, POOL);
    pool_combine_kernel<<<4, 256>>>(POOL, H);
    head1_kernel<<<4, 256>>>(cls_w1, H, Y1);
    headbn_kernel<<<1, 256>>>(Y1, cls_g, cls_b, H2);
    head2_kernel<<<1, 160>>>(cls_w2, H2, out);
}

// round 6
// speedup vs baseline: 1.4865x; 1.0701x over previous
#include <cuda_runtime.h>
#include <cstdint>

#define BB 4
#define NN 4096
#define KNN 9
#define KS 4                      // knn split chunks
#define CHUNK (NN/KS)
#define BN_TOT (BB*NN)
#define NEG_INF (-3.402823466e38f)

// ---------------- device scratch ----------------
__device__ float d_Xt[BN_TOT*3];
__device__ float d_x2[BN_TOT];
__device__ int   d_idx[BN_TOT*KNN];
__device__ float d_candD[BN_TOT*KS*KNN];
__device__ int   d_candI[BN_TOT*KS*KNN];
__device__ float d_G1[BN_TOT*128];
__device__ float d_G2[BN_TOT*256];
__device__ float d_G3[BN_TOT*512];
__device__ float d_G4[BN_TOT*512];
__device__ float d_Gdec[BN_TOT*48];
__device__ float d_cat[BN_TOT*304];
__device__ float d_fused[BN_TOT*256];
__device__ float d_part1[1024*256];
__device__ float d_part2[1024*256];
__device__ __align__(16) float d_scaleA[5][256];
__device__ __align__(16) float d_shiftA[5][256];
__device__ float d_pool[4*16*512];
__device__ float d_h[4*512];
__device__ float d_y1[4*256];
__device__ float d_h2[4*256];

// ---------------- helpers ----------------
__device__ __forceinline__ float tf32_rna(float x) {
    uint32_t u; asm("cvt.rna.tf32.f32 %0, %1;" : "=r"(u) : "f"(x));
    return __uint_as_float(u);
}
__device__ __forceinline__ void mma8(float* d, uint32_t a0, uint32_t a1, uint32_t a2, uint32_t a3,
                                     uint32_t b0, uint32_t b1) {
    asm volatile(
        "mma.sync.aligned.m16n8k8.row.col.f32.tf32.tf32.f32 "
        "{%0,%1,%2,%3},{%4,%5,%6,%7},{%8,%9},{%0,%1,%2,%3};"
        : "+f"(d[0]), "+f"(d[1]), "+f"(d[2]), "+f"(d[3])
        : "r"(a0), "r"(a1), "r"(a2), "r"(a3), "r"(b0), "r"(b1));
}

// ---------------- prep ----------------
__global__ void prep_kernel(const float* __restrict__ x, float* __restrict__ Xt,
                            float* __restrict__ x2) {
    int t = blockIdx.x * blockDim.x + threadIdx.x;
    if (t >= BN_TOT) return;
    int b = t / NN, n = t % NN;
    float a0 = x[(b*3+0)*NN + n];
    float a1 = x[(b*3+1)*NN + n];
    float a2 = x[(b*3+2)*NN + n];
    Xt[t*3+0] = a0; Xt[t*3+1] = a1; Xt[t*3+2] = a2;
    x2[t] = a0*a0 + a1*a1 + a2*a2;
}

// ---------------- knn: chunked partial top-9 ----------------
__global__ void knn_part_kernel(const float* __restrict__ Xt, const float* __restrict__ x2,
                                float* __restrict__ candD, int* __restrict__ candI) {
    __shared__ float sx[CHUNK], sy[CHUNK], sz[CHUNK], s2[CHUNK];
    int b  = blockIdx.x;
    int n  = blockIdx.y * blockDim.x + threadIdx.x;
    int cs = blockIdx.z;
    int m0 = cs * CHUNK;
    const float* Xb = Xt + (size_t)b*NN*3;
    for (int t = threadIdx.x; t < CHUNK; t += blockDim.x) {
        int m = m0 + t;
        sx[t] = Xb[m*3+0];
        sy[t] = Xb[m*3+1];
        sz[t] = Xb[m*3+2];
        s2[t] = x2[b*NN + m];
    }
    __syncthreads();
    float px = Xb[n*3+0], py = Xb[n*3+1], pz = Xb[n*3+2], p2 = x2[b*NN + n];
    float bd[KNN]; int bi[KNN];
#pragma unroll
    for (int j = 0; j < KNN; ++j) { bd[j] = 1e30f; bi[j] = 0; }
#pragma unroll 4
    for (int mm = 0; mm < CHUNK; ++mm) {
        float dot = px*sx[mm] + py*sy[mm] + pz*sz[mm];
        float d = p2 + s2[mm] - 2.0f*dot;
        int m = m0 + mm;
        if (m == n) d = 1e30f;
        if (d < bd[KNN-1]) {
            float vd = d; int vi = m;
#pragma unroll
            for (int j = 0; j < KNN; ++j) {
                if (vd < bd[j]) {
                    float td = bd[j]; bd[j] = vd; vd = td;
                    int   ti = bi[j]; bi[j] = vi; vi = ti;
                }
            }
        }
    }
    size_t base = ((size_t)(b*NN + n)*KS + cs)*KNN;
#pragma unroll
    for (int j = 0; j < KNN; ++j) {
        candD[base + j] = bd[j];
        candI[base + j] = bi[j];
    }
}

__global__ void knn_merge_kernel(const float* __restrict__ candD, const int* __restrict__ candI,
                                 int* __restrict__ idxOut) {
    int t = blockIdx.x * blockDim.x + threadIdx.x;
    if (t >= BN_TOT) return;
    int b = t / NN;
    float bd[KNN]; int bi[KNN];
#pragma unroll
    for (int j = 0; j < KNN; ++j) { bd[j] = 1e30f; bi[j] = 0; }
    size_t base = (size_t)t*KS*KNN;
    for (int c = 0; c < KS*KNN; ++c) {
        float d = candD[base + c];
        int   m = candI[base + c];
        if (d < bd[KNN-1]) {
            float vd = d; int vi = m;
#pragma unroll
            for (int j = 0; j < KNN; ++j) {
                if (vd < bd[j]) {
                    float td = bd[j]; bd[j] = vd; vd = td;
                    int   ti = bi[j]; bi[j] = vi; vi = ti;
                }
            }
        }
    }
#pragma unroll
    for (int j = 0; j < KNN; ++j)
        idxOut[t*KNN + j] = b*NN + bi[j];
}

// ---------------- conv1: Kc=3 fused GEMM (Nc = 128), float4 stores ----------------
__global__ void conv1_kernel(const float* __restrict__ Xt, const float* __restrict__ w1,
                             float* __restrict__ G) {
    __shared__ float cw0[128], cw1[128], cw2[128];
    int tid = threadIdx.x;
    if (tid < 128) {
        if (tid < 64) {
            cw0[tid] = w1[tid*6+0] - w1[tid*6+3];
            cw1[tid] = w1[tid*6+1] - w1[tid*6+4];
            cw2[tid] = w1[tid*6+2] - w1[tid*6+5];
        } else {
            int q = tid - 64;
            cw0[tid] = w1[q*6+3]; cw1[tid] = w1[q*6+4]; cw2[tid] = w1[q*6+5];
        }
    }
    __syncthreads();
    int t4 = blockIdx.x * blockDim.x + tid;        // float4 index
    if (t4 >= BN_TOT*128/4) return;
    int t = t4 * 4;
    int p = t >> 7, o = t & 127;
    float x0 = Xt[p*3+0], x1 = Xt[p*3+1], x2 = Xt[p*3+2];
    float4 r;
    r.x = cw0[o+0]*x0 + cw1[o+0]*x1 + cw2[o+0]*x2;
    r.y = cw0[o+1]*x0 + cw1[o+1]*x1 + cw2[o+1]*x2;
    r.z = cw0[o+2]*x0 + cw1[o+2]*x1 + cw2[o+2]*x2;
    r.w = cw0[o+3]*x0 + cw1[o+3]*x1 + cw2[o+3]*x2;
    *(float4*)&G[t] = r;
}

// ---------------- tf32 3x-split tensor-core GEMM, 2 blocks/SM ----------------
// C[M x Nc] = Aeff[M x Kc] * Weff[Nc x Kc]^T
// Aeff = (scaleStage>=0) ? relu(A*scale+shift) : A      (per-channel k affine)
// Weff = (wmode==1) ? [Wa-Wb ; Wb] from raw w (O x 2Kc) : W (Nc x Kc)
#define BM 128
#define BN 128
#define BK 16
#define SMS 130
#define TSZ (2*BK*SMS)            // per array, double-buffered
#define MMA_SMEM (4*TSZ*4)        // sAh, sAl, sBh, sBl = 66560 B; 2 blocks = 133KB <= 228KB

__global__ __launch_bounds__(256, 2)
void mma_gemm(const float* __restrict__ A, int lda,
              const float* __restrict__ W, int wmode, int O,
              float* __restrict__ C, int Nc, int Kc, int scaleStage) {
    extern __shared__ float smem[];
    float* sAh = smem;
    float* sAl = smem + TSZ;
    float* sBh = smem + 2*TSZ;
    float* sBl = smem + 3*TSZ;

    int tid = threadIdx.x;
    int lane = tid & 31, wid = tid >> 5;
    int wm = wid >> 2, wn = wid & 3;
    int g = lane >> 2, tig = lane & 3;
    int bm = blockIdx.x * BM;
    int bn = blockIdx.y * BN;

    int m0 = tid >> 2;
    int kq = tid & 3;

    float d[4][4][4];
#pragma unroll
    for (int i = 0; i < 4; ++i)
#pragma unroll
        for (int j = 0; j < 4; ++j)
#pragma unroll
            for (int q = 0; q < 4; ++q) d[i][j][q] = 0.0f;

    int nIter = Kc / BK;
    float4 ra[2], rb[2];

    const float* scp = (scaleStage >= 0) ? d_scaleA[scaleStage] : nullptr;
    const float* shp = (scaleStage >= 0) ? d_shiftA[scaleStage] : nullptr;

#define LOAD_TILE(K0)                                                            \
    {                                                                            \
        int k0_ = (K0);                                                          \
        float4 sc4, sh4;                                                         \
        if (scp) {                                                               \
            sc4 = *(const float4*)&scp[k0_ + kq*4];                              \
            sh4 = *(const float4*)&shp[k0_ + kq*4];                              \
        }                                                                        \
        _Pragma("unroll")                                                        \
        for (int i = 0; i < 2; ++i) {                                            \
            ra[i] = *(const float4*)&A[(size_t)(bm + m0 + i*64)*lda + k0_ + kq*4];\
            if (scp) {                                                           \
                ra[i].x = fmaxf(fmaf(ra[i].x, sc4.x, sh4.x), 0.0f);              \
                ra[i].y = fmaxf(fmaf(ra[i].y, sc4.y, sh4.y), 0.0f);              \
                ra[i].z = fmaxf(fmaf(ra[i].z, sc4.z, sh4.z), 0.0f);              \
                ra[i].w = fmaxf(fmaf(ra[i].w, sc4.w, sh4.w), 0.0f);              \
            }                                                                    \
            int n = bn + m0 + i*64;                                              \
            if (wmode == 1) {                                                    \
                if (n < O) {                                                     \
                    float4 wa = *(const float4*)&W[(size_t)n*2*Kc + k0_ + kq*4]; \
                    float4 wb = *(const float4*)&W[(size_t)n*2*Kc + Kc + k0_ + kq*4];\
                    rb[i] = make_float4(wa.x-wb.x, wa.y-wb.y, wa.z-wb.z, wa.w-wb.w);\
                } else {                                                         \
                    rb[i] = *(const float4*)&W[(size_t)(n-O)*2*Kc + Kc + k0_ + kq*4];\
                }                                                                \
            } else {                                                             \
                rb[i] = (n < Nc) ? *(const float4*)&W[(size_t)n*Kc + k0_ + kq*4] \
                                 : make_float4(0.f, 0.f, 0.f, 0.f);              \
            }                                                                    \
        }                                                                        \
    }

#define COMMIT_TILE(BASE)                                                        \
    {                                                                            \
        int base_ = (BASE);                                                      \
        _Pragma("unroll")                                                        \
        for (int i = 0; i < 2; ++i) {                                            \
            float av[4] = {ra[i].x, ra[i].y, ra[i].z, ra[i].w};                  \
            float bv[4] = {rb[i].x, rb[i].y, rb[i].z, rb[i].w};                  \
            _Pragma("unroll")                                                    \
            for (int j = 0; j < 4; ++j) {                                        \
                int kk = kq*4 + j, mm = m0 + i*64;                               \
                float ah = tf32_rna(av[j]);                                      \
                sAh[base_ + kk*SMS + mm] = ah;                                   \
                sAl[base_ + kk*SMS + mm] = tf32_rna(av[j] - ah);                 \
                float bh = tf32_rna(bv[j]);                                      \
                sBh[base_ + kk*SMS + mm] = bh;                                   \
                sBl[base_ + kk*SMS + mm] = tf32_rna(bv[j] - bh);                 \
            }                                                                    \
        }                                                                        \
    }

    LOAD_TILE(0)
    COMMIT_TILE(0)
    __syncthreads();

    for (int it = 0; it < nIter; ++it) {
        int buf = it & 1;
        int base = buf * (BK*SMS);
        bool more = (it + 1 < nIter);
        if (more) LOAD_TILE((it + 1) * BK)

#pragma unroll
        for (int ks = 0; ks < 2; ++ks) {
            int k1 = base + (ks*8 + tig)*SMS;
            int k2 = base + (ks*8 + tig + 4)*SMS;
            uint32_t bh[4][2], bl[4][2];
#pragma unroll
            for (int nt = 0; nt < 4; ++nt) {
                int c = wn*32 + nt*8 + g;
                bh[nt][0] = __float_as_uint(sBh[k1 + c]);
                bh[nt][1] = __float_as_uint(sBh[k2 + c]);
                bl[nt][0] = __float_as_uint(sBl[k1 + c]);
                bl[nt][1] = __float_as_uint(sBl[k2 + c]);
            }
            // pass 1: Ah x (Bh + Bl)
            {
                uint32_t ah[4][4];
#pragma unroll
                for (int mt = 0; mt < 4; ++mt) {
                    int r = wm*64 + mt*16 + g;
                    ah[mt][0] = __float_as_uint(sAh[k1 + r]);
                    ah[mt][1] = __float_as_uint(sAh[k1 + r + 8]);
                    ah[mt][2] = __float_as_uint(sAh[k2 + r]);
                    ah[mt][3] = __float_as_uint(sAh[k2 + r + 8]);
                }
#pragma unroll
                for (int mt = 0; mt < 4; ++mt)
#pragma unroll
                    for (int nt = 0; nt < 4; ++nt) {
                        mma8(d[mt][nt], ah[mt][0], ah[mt][1], ah[mt][2], ah[mt][3],
                             bl[nt][0], bl[nt][1]);
                        mma8(d[mt][nt], ah[mt][0], ah[mt][1], ah[mt][2], ah[mt][3],
                             bh[nt][0], bh[nt][1]);
                    }
            }
            // pass 2: Al x Bh
            {
                uint32_t al[4][4];
#pragma unroll
                for (int mt = 0; mt < 4; ++mt) {
                    int r = wm*64 + mt*16 + g;
                    al[mt][0] = __float_as_uint(sAl[k1 + r]);
                    al[mt][1] = __float_as_uint(sAl[k1 + r + 8]);
                    al[mt][2] = __float_as_uint(sAl[k2 + r]);
                    al[mt][3] = __float_as_uint(sAl[k2 + r + 8]);
                }
#pragma unroll
                for (int mt = 0; mt < 4; ++mt)
#pragma unroll
                    for (int nt = 0; nt < 4; ++nt)
                        mma8(d[mt][nt], al[mt][0], al[mt][1], al[mt][2], al[mt][3],
                             bh[nt][0], bh[nt][1]);
            }
        }

        if (more) COMMIT_TILE((buf ^ 1) * (BK*SMS))
        __syncthreads();
    }

#pragma unroll
    for (int mt = 0; mt < 4; ++mt) {
        int row = bm + wm*64 + mt*16 + g;
#pragma unroll
        for (int nt = 0; nt < 4; ++nt) {
            int col = bn + wn*32 + nt*8 + tig*2;
            if (col < Nc) {
                *(float2*)&C[(size_t)row*Nc + col]     = make_float2(d[mt][nt][0], d[mt][nt][1]);
                *(float2*)&C[(size_t)(row+8)*Nc + col] = make_float2(d[mt][nt][2], d[mt][nt][3]);
            }
        }
    }
#undef LOAD_TILE
#undef COMMIT_TILE
}

// ---------------- edge pass: 256 threads, points x channels packing ----------------
__global__ void edge_kernel(float* __restrict__ G, const int* __restrict__ idx,
                            int O, float* __restrict__ part1, float* __restrict__ part2) {
    int tid = threadIdx.x;
    int o = tid % O;
    int pr = tid / O;
    int R = 256 / O;
    int blk = blockIdx.x;
    int p0 = blk * 16;
    __shared__ int sidx[16*KNN];
    for (int t = tid; t < 16*KNN; t += 256)
        sidx[t] = idx[p0*KNN + t];
    __syncthreads();
    int S = 2*O;
    float s1 = 0.0f, s2 = 0.0f;
    for (int pp = pr; pp < 16; pp += R) {
        int p = p0 + pp;
        float u = G[(size_t)p*S + o];
        float zmax = NEG_INF;
#pragma unroll
        for (int k = 0; k < KNN; ++k) {
            int j = sidx[pp*KNN + k];
            float z = G[(size_t)j*S + O + o];
            float v = u + z;
            zmax = fmaxf(zmax, z);
            s1 += v;
            s2 += v*v;
        }
        G[(size_t)p*S + o] = u + zmax;
    }
    __shared__ float red1[256], red2[256];
    red1[tid] = s1; red2[tid] = s2;
    __syncthreads();
    for (int r = R >> 1; r > 0; r >>= 1) {
        if (pr < r) {
            red1[tid] += red1[tid + r*O];
            red2[tid] += red2[tid + r*O];
        }
        __syncthreads();
    }
    if (pr == 0) {
        part1[blk*O + o] = red1[tid];
        part2[blk*O + o] = red2[tid];
    }
}

// ---------------- parallel stats reduce: one block per channel ----------------
__global__ void reduce_stats_kernel(const float* __restrict__ part1,
                                    const float* __restrict__ part2,
                                    const float* __restrict__ g, const float* __restrict__ b,
                                    int O, float invCnt, int stage) {
    int o = blockIdx.x;
    int tid = threadIdx.x;
    float s1 = 0.0f, s2 = 0.0f;
    for (int i = tid; i < 1024; i += 256) {
        s1 += part1[(size_t)i*O + o];
        s2 += part2[(size_t)i*O + o];
    }
    __shared__ float r1[256], r2[256];
    r1[tid] = s1; r2[tid] = s2;
    __syncthreads();
    for (int s = 128; s > 0; s >>= 1) {
        if (tid < s) { r1[tid] += r1[tid + s]; r2[tid] += r2[tid + s]; }
        __syncthreads();
    }
    if (tid == 0) {
        float mean = r1[0] * invCnt;
        float var  = r2[0] * invCnt - mean*mean;
        float sc = g[o] * rsqrtf(var + 1e-5f);
        d_scaleA[stage][o] = sc;
        d_shiftA[stage][o] = b[o] - mean * sc;
    }
}

// ---------------- column stats over BN rows (dec path) ----------------
__global__ void colstats_kernel(const float* __restrict__ X, int O, float invCnt,
                                const float* __restrict__ g, const float* __restrict__ b,
                                int stage) {
    int o = blockIdx.x;
    __shared__ float r1[256], r2[256];
    float s1 = 0.0f, s2 = 0.0f;
    for (int r = threadIdx.x; r < BN_TOT; r += 256) {
        float v = X[(size_t)r*O + o];
        s1 += v; s2 += v*v;
    }
    r1[threadIdx.x] = s1; r2[threadIdx.x] = s2;
    __syncthreads();
    for (int s = 128; s > 0; s >>= 1) {
        if (threadIdx.x < s) {
            r1[threadIdx.x] += r1[threadIdx.x + s];
            r2[threadIdx.x] += r2[threadIdx.x + s];
        }
        __syncthreads();
    }
    if (threadIdx.x == 0) {
        float mean = r1[0] * invCnt;
        float var  = r2[0] * invCnt - mean*mean;
        float sc = g[o] * rsqrtf(var + 1e-5f);
        d_scaleA[stage][o] = sc;
        d_shiftA[stage][o] = b[o] - mean * sc;
    }
}

// ---------------- cat with fused affines ----------------
__global__ void cat_kernel(const float* __restrict__ G4, const float* __restrict__ Gdec,
                           float* __restrict__ cat) {
    int t = blockIdx.x * blockDim.x + threadIdx.x;
    if (t >= BN_TOT*304) return;
    int p = t / 304, c = t % 304;
    float v;
    if (c < 256)
        v = fmaxf(fmaf(G4[(size_t)p*512 + c], d_scaleA[3][c], d_shiftA[3][c]), 0.0f);
    else {
        int q = c - 256;
        v = fmaxf(fmaf(Gdec[(size_t)p*48 + q], d_scaleA[4][q], d_shiftA[4][q]), 0.0f);
    }
    cat[t] = v;
}

// ---------------- pooling ----------------
__global__ void pool_partial_kernel(const float* __restrict__ fused, float* __restrict__ pool) {
    int b = blockIdx.x, ch = blockIdx.y, o = threadIdx.x;
    int n0 = ch * 256;
    float mx = NEG_INF, sm = 0.0f;
    for (int i = 0; i < 256; ++i) {
        float v = fused[((size_t)(b*NN + n0 + i))*256 + o];
        mx = fmaxf(mx, v);
        sm += v;
    }
    pool[((size_t)(b*16 + ch))*512 + o]       = mx;
    pool[((size_t)(b*16 + ch))*512 + 256 + o] = sm;
}

__global__ void pool_combine_kernel(const float* __restrict__ pool, float* __restrict__ h) {
    int b = blockIdx.x, o = threadIdx.x;
    float mx = NEG_INF, sm = 0.0f;
    for (int c = 0; c < 16; ++c) {
        mx = fmaxf(mx, pool[((size_t)(b*16 + c))*512 + o]);
        sm += pool[((size_t)(b*16 + c))*512 + 256 + o];
    }
    h[b*512 + o]       = mx;
    h[b*512 + 256 + o] = sm * (1.0f / (float)NN);
}

// ---------------- classifier head ----------------
__global__ void head1_kernel(const float* __restrict__ w, const float* __restrict__ h,
                             float* __restrict__ y1) {
    int b = blockIdx.x, o = threadIdx.x;
    float acc = 0.0f;
    for (int c = 0; c < 512; ++c)
        acc = fmaf(w[o*512 + c], h[b*512 + c], acc);
    y1[b*256 + o] = acc;
}

__global__ void headbn_kernel(const float* __restrict__ y1, const float* __restrict__ g,
                              const float* __restrict__ b, float* __restrict__ h2) {
    int o = threadIdx.x;
    float v0 = y1[0*256 + o], v1 = y1[1*256 + o], v2 = y1[2*256 + o], v3 = y1[3*256 + o];
    float m = 0.25f * (v0 + v1 + v2 + v3);
    float q0 = v0 - m, q1 = v1 - m, q2 = v2 - m, q3 = v3 - m;
    float var = 0.25f * (q0*q0 + q1*q1 + q2*q2 + q3*q3);
    float sc = g[o] * rsqrtf(var + 1e-5f);
    float bo = b[o];
    h2[0*256 + o] = fmaxf(q0*sc + bo, 0.0f);
    h2[1*256 + o] = fmaxf(q1*sc + bo, 0.0f);
    h2[2*256 + o] = fmaxf(q2*sc + bo, 0.0f);
    h2[3*256 + o] = fmaxf(q3*sc + bo, 0.0f);
}

__global__ void head2_kernel(const float* __restrict__ w, const float* __restrict__ h2,
                             float* __restrict__ out) {
    int t = threadIdx.x;
    if (t >= 160) return;
    int b = t / 40, q = t % 40;
    float acc = 0.0f;
    for (int c = 0; c < 256; ++c)
        acc = fmaf(w[q*256 + c], h2[b*256 + c], acc);
    out[b*40 + q] = acc;
}

// ---------------- host driver ----------------
static float* getF(const void* sym) { void* p = nullptr; cudaGetSymbolAddress(&p, sym); return (float*)p; }

extern "C" void kernel_launch(void* const* d_in, const int* in_sizes, int n_in,
                              void* d_out, int out_size) {
    const float* x      = (const float*)d_in[0];
    const float* w1     = (const float*)d_in[2];
    const float* g1     = (const float*)d_in[3];
    const float* b1     = (const float*)d_in[4];
    const float* w2     = (const float*)d_in[5];
    const float* g2     = (const float*)d_in[6];
    const float* b2     = (const float*)d_in[7];
    const float* w3     = (const float*)d_in[8];
    const float* g3     = (const float*)d_in[9];
    const float* b3     = (const float*)d_in[10];
    const float* w4     = (const float*)d_in[11];
    const float* g4     = (const float*)d_in[12];
    const float* b4     = (const float*)d_in[13];
    const float* dec_w  = (const float*)d_in[14];
    const float* dec_g  = (const float*)d_in[15];
    const float* dec_b  = (const float*)d_in[16];
    const float* fus_w  = (const float*)d_in[17];
    const float* cls_w1 = (const float*)d_in[18];
    const float* cls_g  = (const float*)d_in[19];
    const float* cls_b  = (const float*)d_in[20];
    const float* cls_w2 = (const float*)d_in[21];
    float* out = (float*)d_out;

    float* Xt   = getF(d_Xt);
    float* X2   = getF(d_x2);
    float* CD   = getF(d_candD);
    float* G1   = getF(d_G1);
    float* G2   = getF(d_G2);
    float* G3   = getF(d_G3);
    float* G4   = getF(d_G4);
    float* GD   = getF(d_Gdec);
    float* CAT  = getF(d_cat);
    float* FUS  = getF(d_fused);
    float* P1   = getF(d_part1);
    float* P2   = getF(d_part2);
    float* POOL = getF(d_pool);
    float* H    = getF(d_h);
    float* Y1   = getF(d_y1);
    float* H2   = getF(d_h2);
    void* ip = nullptr; cudaGetSymbolAddress(&ip, d_idx);
    int* IDX = (int*)ip;
    void* cp = nullptr; cudaGetSymbolAddress(&cp, d_candI);
    int* CI = (int*)cp;

    static int attr_done = 0;
    if (!attr_done) {
        cudaFuncSetAttribute(mma_gemm, cudaFuncAttributeMaxDynamicSharedMemorySize, MMA_SMEM);
        attr_done = 1;
    }

    // prep + knn (chunked)
    prep_kernel<<<(BN_TOT + 255)/256, 256>>>(x, Xt, X2);
    knn_part_kernel<<<dim3(BB, NN/128, KS), 128>>>(Xt, X2, CD, CI);
    knn_merge_kernel<<<(BN_TOT + 255)/256, 256>>>(CD, CI, IDX);

    // conv1 (Kc=3 special)
    conv1_kernel<<<BN_TOT*128/4/256, 256>>>(Xt, w1, G1);
    edge_kernel<<<1024, 256>>>(G1, IDX, 64, P1, P2);
    reduce_stats_kernel<<<64, 256>>>(P1, P2, g1, b1, 64, 1.0f/(float)(BN_TOT*KNN), 0);

    // conv2: A = relu(aff0(G1[:, :64])), W folded from w2 (128 x 128)
    mma_gemm<<<dim3(BN_TOT/BM, 2), 256, MMA_SMEM>>>(G1, 128, w2, 1, 128, G2, 256, 64, 0);
    edge_kernel<<<1024, 256>>>(G2, IDX, 128, P1, P2);
    reduce_stats_kernel<<<128, 256>>>(P1, P2, g2, b2, 128, 1.0f/(float)(BN_TOT*KNN), 1);

    // conv3
    mma_gemm<<<dim3(BN_TOT/BM, 4), 256, MMA_SMEM>>>(G2, 256, w3, 1, 256, G3, 512, 128, 1);
    edge_kernel<<<1024, 256>>>(G3, IDX, 256, P1, P2);
    reduce_stats_kernel<<<256, 256>>>(P1, P2, g3, b3, 256, 1.0f/(float)(BN_TOT*KNN), 2);

    // conv4
    mma_gemm<<<dim3(BN_TOT/BM, 4), 256, MMA_SMEM>>>(G3, 512, w4, 1, 256, G4, 512, 256, 2);
    edge_kernel<<<1024, 256>>>(G4, IDX, 256, P1, P2);
    reduce_stats_kernel<<<256, 256>>>(P1, P2, g4, b4, 256, 1.0f/(float)(BN_TOT*KNN), 3);

    // decoder: Gdec = relu(aff0(G1[:, :64])) @ dec_w^T
    mma_gemm<<<dim3(BN_TOT/BM, 1), 256, MMA_SMEM>>>(G1, 128, dec_w, 0, 0, GD, 48, 64, 0);
    colstats_kernel<<<48, 256>>>(GD, 48, 1.0f/(float)BN_TOT, dec_g, dec_b, 4);

    // fused concat (applies aff3 on G4 part, aff4 on dec part)
    cat_kernel<<<(BN_TOT*304 + 255)/256, 256>>>(G4, GD, CAT);
    mma_gemm<<<dim3(BN_TOT/BM, 2), 256, MMA_SMEM>>>(CAT, 304, fus_w, 0, 0, FUS, 256, 304, -1);

    // pool + head
    pool_partial_kernel<<<dim3(4, 16), 256>>>(FUS, POOL);
    pool_combine_kernel<<<4, 256>>>(POOL, H);
    head1_kernel<<<4, 256>>>(cls_w1, H, Y1);
    headbn_kernel<<<1, 256>>>(Y1, cls_g, cls_b, H2);
    head2_kernel<<<1, 160>>>(cls_w2, H2, out);
}

// round 9
// speedup vs baseline: 2.0393x; 1.3719x over previous
#include <cuda_runtime.h>
#include <cstdint>

#define BB 4
#define NN 4096
#define KNN 9
#define KS 4                      // knn split chunks
#define CHUNK (NN/KS)
#define BN_TOT (BB*NN)
#define NEG_INF (-3.402823466e38f)

// ---------------- device scratch ----------------
__device__ float d_Xt[BN_TOT*3];
__device__ float d_x2[BN_TOT];
__device__ int   d_idx[BN_TOT*KNN];
__device__ float d_candD[BN_TOT*KS*KNN];
__device__ int   d_candI[BN_TOT*KS*KNN];
__device__ float d_G1[BN_TOT*128];
__device__ float d_G2[BN_TOT*256];
__device__ float d_G3[BN_TOT*512];
__device__ float d_G4[BN_TOT*512];
__device__ float d_Gdec[BN_TOT*48];
__device__ float d_cat[BN_TOT*304];
__device__ float d_fused[BN_TOT*256];
__device__ float d_part1[1024*256];
__device__ float d_part2[1024*256];
__device__ __align__(16) float d_scaleA[5][256];
__device__ __align__(16) float d_shiftA[5][256];
__device__ float d_pool[4*16*512];
__device__ float d_h[4*512];
__device__ float d_y1[4*256];
__device__ float d_h2[4*256];

// ---------------- helpers ----------------
// pack two floats as bf16x2: low half = a0, high half = a1
__device__ __forceinline__ uint32_t pack_bf16(float a0, float a1) {
    uint32_t r; asm("cvt.rn.bf16x2.f32 %0, %1, %2;" : "=r"(r) : "f"(a1), "f"(a0));
    return r;
}
__device__ __forceinline__ void mma16(float* d, uint32_t a0, uint32_t a1, uint32_t a2, uint32_t a3,
                                      uint32_t b0, uint32_t b1) {
    asm volatile(
        "mma.sync.aligned.m16n8k16.row.col.f32.bf16.bf16.f32 "
        "{%0,%1,%2,%3},{%4,%5,%6,%7},{%8,%9},{%0,%1,%2,%3};"
        : "+f"(d[0]), "+f"(d[1]), "+f"(d[2]), "+f"(d[3])
        : "r"(a0), "r"(a1), "r"(a2), "r"(a3), "r"(b0), "r"(b1));
}

// ---------------- prep ----------------
__global__ void prep_kernel(const float* __restrict__ x, float* __restrict__ Xt,
                            float* __restrict__ x2) {
    int t = blockIdx.x * blockDim.x + threadIdx.x;
    if (t >= BN_TOT) return;
    int b = t / NN, n = t % NN;
    float a0 = x[(b*3+0)*NN + n];
    float a1 = x[(b*3+1)*NN + n];
    float a2 = x[(b*3+2)*NN + n];
    Xt[t*3+0] = a0; Xt[t*3+1] = a1; Xt[t*3+2] = a2;
    x2[t] = a0*a0 + a1*a1 + a2*a2;
}

// ---------------- knn: chunked partial top-9 ----------------
__global__ void knn_part_kernel(const float* __restrict__ Xt, const float* __restrict__ x2,
                                float* __restrict__ candD, int* __restrict__ candI) {
    __shared__ float sx[CHUNK], sy[CHUNK], sz[CHUNK], s2[CHUNK];
    int b  = blockIdx.x;
    int n  = blockIdx.y * blockDim.x + threadIdx.x;
    int cs = blockIdx.z;
    int m0 = cs * CHUNK;
    const float* Xb = Xt + (size_t)b*NN*3;
    for (int t = threadIdx.x; t < CHUNK; t += blockDim.x) {
        int m = m0 + t;
        sx[t] = Xb[m*3+0];
        sy[t] = Xb[m*3+1];
        sz[t] = Xb[m*3+2];
        s2[t] = x2[b*NN + m];
    }
    __syncthreads();
    float px = Xb[n*3+0], py = Xb[n*3+1], pz = Xb[n*3+2], p2 = x2[b*NN + n];
    float bd[KNN]; int bi[KNN];
#pragma unroll
    for (int j = 0; j < KNN; ++j) { bd[j] = 1e30f; bi[j] = 0; }
#pragma unroll 4
    for (int mm = 0; mm < CHUNK; ++mm) {
        float dot = px*sx[mm] + py*sy[mm] + pz*sz[mm];
        float d = p2 + s2[mm] - 2.0f*dot;
        int m = m0 + mm;
        if (m == n) d = 1e30f;
        if (d < bd[KNN-1]) {
            float vd = d; int vi = m;
#pragma unroll
            for (int j = 0; j < KNN; ++j) {
                if (vd < bd[j]) {
                    float td = bd[j]; bd[j] = vd; vd = td;
                    int   ti = bi[j]; bi[j] = vi; vi = ti;
                }
            }
        }
    }
    size_t base = ((size_t)(b*NN + n)*KS + cs)*KNN;
#pragma unroll
    for (int j = 0; j < KNN; ++j) {
        candD[base + j] = bd[j];
        candI[base + j] = bi[j];
    }
}

__global__ void knn_merge_kernel(const float* __restrict__ candD, const int* __restrict__ candI,
                                 int* __restrict__ idxOut) {
    int t = blockIdx.x * blockDim.x + threadIdx.x;
    if (t >= BN_TOT) return;
    int b = t / NN;
    float bd[KNN]; int bi[KNN];
#pragma unroll
    for (int j = 0; j < KNN; ++j) { bd[j] = 1e30f; bi[j] = 0; }
    size_t base = (size_t)t*KS*KNN;
    for (int c = 0; c < KS*KNN; ++c) {
        float d = candD[base + c];
        int   m = candI[base + c];
        if (d < bd[KNN-1]) {
            float vd = d; int vi = m;
#pragma unroll
            for (int j = 0; j < KNN; ++j) {
                if (vd < bd[j]) {
                    float td = bd[j]; bd[j] = vd; vd = td;
                    int   ti = bi[j]; bi[j] = vi; vi = ti;
                }
            }
        }
    }
#pragma unroll
    for (int j = 0; j < KNN; ++j)
        idxOut[t*KNN + j] = b*NN + bi[j];
}

// ---------------- conv1: Kc=3 fused GEMM (Nc = 128), float4 stores ----------------
__global__ void conv1_kernel(const float* __restrict__ Xt, const float* __restrict__ w1,
                             float* __restrict__ G) {
    __shared__ float cw0[128], cw1[128], cw2[128];
    int tid = threadIdx.x;
    if (tid < 128) {
        if (tid < 64) {
            cw0[tid] = w1[tid*6+0] - w1[tid*6+3];
            cw1[tid] = w1[tid*6+1] - w1[tid*6+4];
            cw2[tid] = w1[tid*6+2] - w1[tid*6+5];
        } else {
            int q = tid - 64;
            cw0[tid] = w1[q*6+3]; cw1[tid] = w1[q*6+4]; cw2[tid] = w1[q*6+5];
        }
    }
    __syncthreads();
    int t4 = blockIdx.x * blockDim.x + tid;        // float4 index
    if (t4 >= BN_TOT*128/4) return;
    int t = t4 * 4;
    int p = t >> 7, o = t & 127;
    float x0 = Xt[p*3+0], x1 = Xt[p*3+1], x2 = Xt[p*3+2];
    float4 r;
    r.x = cw0[o+0]*x0 + cw1[o+0]*x1 + cw2[o+0]*x2;
    r.y = cw0[o+1]*x0 + cw1[o+1]*x1 + cw2[o+1]*x2;
    r.z = cw0[o+2]*x0 + cw1[o+2]*x1 + cw2[o+2]*x2;
    r.w = cw0[o+3]*x0 + cw1[o+3]*x1 + cw2[o+3]*x2;
    *(float4*)&G[t] = r;
}

// ---------------- bf16x3 (Ootomo) tensor-core GEMM, 2 blocks/SM ----------------
// C[M x Nc] = Aeff[M x Kc] * Weff[Nc x Kc]^T
// A = Ah + Al (bf16 split), W = Bh + Bl; D = Ah*Bl + Al*Bh + Ah*Bh (al*bl dropped ~2^-16)
// Aeff = (scaleStage>=0) ? relu(A*scale+shift) : A      (per-channel k affine)
// Weff = (wmode==1) ? [Wa-Wb ; Wb] from raw w (O x 2Kc) : W (Nc x Kc)
#define BM 128
#define BN 128
#define BK 16
#define K2 8                       // bf16x2 pairs per BK
#define SMS2 136                   // uint32 stride per k2-row (conflict-free frag loads)
#define TSZ2 (2*K2*SMS2)           // per array (double-buffered), in uint32
#define MMA_SMEM (4*TSZ2*4)        // sAh, sAl, sBh, sBl bytes = 34816

__global__ __launch_bounds__(256, 2)
void mma_gemm(const float* __restrict__ A, int lda,
              const float* __restrict__ W, int wmode, int O,
              float* __restrict__ C, int Nc, int Kc, int scaleStage) {
    extern __shared__ uint32_t smemu[];
    uint32_t* sAh = smemu;
    uint32_t* sAl = smemu + TSZ2;
    uint32_t* sBh = smemu + 2*TSZ2;
    uint32_t* sBl = smemu + 3*TSZ2;

    int tid = threadIdx.x;
    int lane = tid & 31, wid = tid >> 5;
    int wm = wid >> 2, wn = wid & 3;       // 2 x 4 warp grid; warp tile 64 x 32
    int g = lane >> 2, tig = lane & 3;
    int bm = blockIdx.x * BM;
    int bn = blockIdx.y * BN;

    int m0 = tid >> 2;                     // 0..63
    int kq = tid & 3;                      // float4 slot within BK

    float d[4][4][4];
#pragma unroll
    for (int i = 0; i < 4; ++i)
#pragma unroll
        for (int j = 0; j < 4; ++j)
#pragma unroll
            for (int q = 0; q < 4; ++q) d[i][j][q] = 0.0f;

    int nIter = Kc / BK;
    float4 ra[2], rb[2];

    const float* scp = (scaleStage >= 0) ? d_scaleA[scaleStage] : nullptr;
    const float* shp = (scaleStage >= 0) ? d_shiftA[scaleStage] : nullptr;

#define LOAD_TILE(K0)                                                            \
    {                                                                            \
        int k0_ = (K0);                                                          \
        float4 sc4, sh4;                                                         \
        if (scp) {                                                               \
            sc4 = *(const float4*)&scp[k0_ + kq*4];                              \
            sh4 = *(const float4*)&shp[k0_ + kq*4];                              \
        }                                                                        \
        _Pragma("unroll")                                                        \
        for (int i = 0; i < 2; ++i) {                                            \
            ra[i] = *(const float4*)&A[(size_t)(bm + m0 + i*64)*lda + k0_ + kq*4];\
            if (scp) {                                                           \
                ra[i].x = fmaxf(fmaf(ra[i].x, sc4.x, sh4.x), 0.0f);              \
                ra[i].y = fmaxf(fmaf(ra[i].y, sc4.y, sh4.y), 0.0f);              \
                ra[i].z = fmaxf(fmaf(ra[i].z, sc4.z, sh4.z), 0.0f);              \
                ra[i].w = fmaxf(fmaf(ra[i].w, sc4.w, sh4.w), 0.0f);              \
            }                                                                    \
            int n = bn + m0 + i*64;                                              \
            if (wmode == 1) {                                                    \
                if (n < O) {                                                     \
                    float4 wa = *(const float4*)&W[(size_t)n*2*Kc + k0_ + kq*4]; \
                    float4 wb = *(const float4*)&W[(size_t)n*2*Kc + Kc + k0_ + kq*4];\
                    rb[i] = make_float4(wa.x-wb.x, wa.y-wb.y, wa.z-wb.z, wa.w-wb.w);\
                } else {                                                         \
                    rb[i] = *(const float4*)&W[(size_t)(n-O)*2*Kc + Kc + k0_ + kq*4];\
                }                                                                \
            } else {                                                             \
                rb[i] = (n < Nc) ? *(const float4*)&W[(size_t)n*Kc + k0_ + kq*4] \
                                 : make_float4(0.f, 0.f, 0.f, 0.f);              \
            }                                                                    \
        }                                                                        \
    }

// split 4 consecutive floats into 2 bf16x2 hi pairs + 2 lo pairs, store at k2 rows
#define COMMIT_ROW(arrH, arrL, base_, mm_, v0, v1, v2, v3)                        \
    {                                                                            \
        uint32_t h0 = pack_bf16(v0, v1);                                         \
        uint32_t h1 = pack_bf16(v2, v3);                                         \
        float l0a = (v0) - __uint_as_float(h0 << 16);                            \
        float l0b = (v1) - __uint_as_float(h0 & 0xffff0000u);                    \
        float l1a = (v2) - __uint_as_float(h1 << 16);                            \
        float l1b = (v3) - __uint_as_float(h1 & 0xffff0000u);                    \
        arrH[(base_) + (kq*2+0)*SMS2 + (mm_)] = h0;                              \
        arrH[(base_) + (kq*2+1)*SMS2 + (mm_)] = h1;                              \
        arrL[(base_) + (kq*2+0)*SMS2 + (mm_)] = pack_bf16(l0a, l0b);             \
        arrL[(base_) + (kq*2+1)*SMS2 + (mm_)] = pack_bf16(l1a, l1b);             \
    }

#define COMMIT_TILE(BASE)                                                        \
    {                                                                            \
        int base_ = (BASE);                                                      \
        _Pragma("unroll")                                                        \
        for (int i = 0; i < 2; ++i) {                                            \
            int mm = m0 + i*64;                                                  \
            COMMIT_ROW(sAh, sAl, base_, mm, ra[i].x, ra[i].y, ra[i].z, ra[i].w)  \
            COMMIT_ROW(sBh, sBl, base_, mm, rb[i].x, rb[i].y, rb[i].z, rb[i].w)  \
        }                                                                        \
    }

    LOAD_TILE(0)
    COMMIT_TILE(0)
    __syncthreads();

    for (int it = 0; it < nIter; ++it) {
        int buf = it & 1;
        int base = buf * (K2*SMS2);
        bool more = (it + 1 < nIter);
        if (more) LOAD_TILE((it + 1) * BK)

        {
            int kr1 = base + tig*SMS2;
            int kr2 = base + (tig+4)*SMS2;
            uint32_t bh[4][2], bl[4][2];
#pragma unroll
            for (int nt = 0; nt < 4; ++nt) {
                int c = wn*32 + nt*8 + g;
                bh[nt][0] = sBh[kr1 + c];
                bh[nt][1] = sBh[kr2 + c];
                bl[nt][0] = sBl[kr1 + c];
                bl[nt][1] = sBl[kr2 + c];
            }
            // pass 1: Ah x (Bl then Bh)
            {
                uint32_t ah[4][4];
#pragma unroll
                for (int mt = 0; mt < 4; ++mt) {
                    int r = wm*64 + mt*16 + g;
                    ah[mt][0] = sAh[kr1 + r];
                    ah[mt][1] = sAh[kr1 + r + 8];
                    ah[mt][2] = sAh[kr2 + r];
                    ah[mt][3] = sAh[kr2 + r + 8];
                }
#pragma unroll
                for (int mt = 0; mt < 4; ++mt)
#pragma unroll
                    for (int nt = 0; nt < 4; ++nt) {
                        mma16(d[mt][nt], ah[mt][0], ah[mt][1], ah[mt][2], ah[mt][3],
                              bl[nt][0], bl[nt][1]);
                        mma16(d[mt][nt], ah[mt][0], ah[mt][1], ah[mt][2], ah[mt][3],
                              bh[nt][0], bh[nt][1]);
                    }
            }
            // pass 2: Al x Bh
            {
                uint32_t al[4][4];
#pragma unroll
                for (int mt = 0; mt < 4; ++mt) {
                    int r = wm*64 + mt*16 + g;
                    al[mt][0] = sAl[kr1 + r];
                    al[mt][1] = sAl[kr1 + r + 8];
                    al[mt][2] = sAl[kr2 + r];
                    al[mt][3] = sAl[kr2 + r + 8];
                }
#pragma unroll
                for (int mt = 0; mt < 4; ++mt)
#pragma unroll
                    for (int nt = 0; nt < 4; ++nt)
                        mma16(d[mt][nt], al[mt][0], al[mt][1], al[mt][2], al[mt][3],
                              bh[nt][0], bh[nt][1]);
            }
        }

        if (more) COMMIT_TILE((buf ^ 1) * (K2*SMS2))
        __syncthreads();
    }

#pragma unroll
    for (int mt = 0; mt < 4; ++mt) {
        int row = bm + wm*64 + mt*16 + g;
#pragma unroll
        for (int nt = 0; nt < 4; ++nt) {
            int col = bn + wn*32 + nt*8 + tig*2;
            if (col < Nc) {
                *(float2*)&C[(size_t)row*Nc + col]     = make_float2(d[mt][nt][0], d[mt][nt][1]);
                *(float2*)&C[(size_t)(row+8)*Nc + col] = make_float2(d[mt][nt][2], d[mt][nt][3]);
            }
        }
    }
#undef LOAD_TILE
#undef COMMIT_ROW
#undef COMMIT_TILE
}

// ---------------- edge pass: 256 threads, points x channels packing ----------------
__global__ void edge_kernel(float* __restrict__ G, const int* __restrict__ idx,
                            int O, float* __restrict__ part1, float* __restrict__ part2) {
    int tid = threadIdx.x;
    int o = tid % O;
    int pr = tid / O;
    int R = 256 / O;
    int blk = blockIdx.x;
    int p0 = blk * 16;
    __shared__ int sidx[16*KNN];
    for (int t = tid; t < 16*KNN; t += 256)
        sidx[t] = idx[p0*KNN + t];
    __syncthreads();
    int S = 2*O;
    float s1 = 0.0f, s2 = 0.0f;
    for (int pp = pr; pp < 16; pp += R) {
        int p = p0 + pp;
        float u = G[(size_t)p*S + o];
        float zmax = NEG_INF;
#pragma unroll
        for (int k = 0; k < KNN; ++k) {
            int j = sidx[pp*KNN + k];
            float z = G[(size_t)j*S + O + o];
            float v = u + z;
            zmax = fmaxf(zmax, z);
            s1 += v;
            s2 += v*v;
        }
        G[(size_t)p*S + o] = u + zmax;
    }
    __shared__ float red1[256], red2[256];
    red1[tid] = s1; red2[tid] = s2;
    __syncthreads();
    for (int r = R >> 1; r > 0; r >>= 1) {
        if (pr < r) {
            red1[tid] += red1[tid + r*O];
            red2[tid] += red2[tid + r*O];
        }
        __syncthreads();
    }
    if (pr == 0) {
        part1[blk*O + o] = red1[tid];
        part2[blk*O + o] = red2[tid];
    }
}

// ---------------- parallel stats reduce: one block per channel ----------------
__global__ void reduce_stats_kernel(const float* __restrict__ part1,
                                    const float* __restrict__ part2,
                                    const float* __restrict__ g, const float* __restrict__ b,
                                    int O, float invCnt, int stage) {
    int o = blockIdx.x;
    int tid = threadIdx.x;
    float s1 = 0.0f, s2 = 0.0f;
    for (int i = tid; i < 1024; i += 256) {
        s1 += part1[(size_t)i*O + o];
        s2 += part2[(size_t)i*O + o];
    }
    __shared__ float r1[256], r2[256];
    r1[tid] = s1; r2[tid] = s2;
    __syncthreads();
    for (int s = 128; s > 0; s >>= 1) {
        if (tid < s) { r1[tid] += r1[tid + s]; r2[tid] += r2[tid + s]; }
        __syncthreads();
    }
    if (tid == 0) {
        float mean = r1[0] * invCnt;
        float var  = r2[0] * invCnt - mean*mean;
        float sc = g[o] * rsqrtf(var + 1e-5f);
        d_scaleA[stage][o] = sc;
        d_shiftA[stage][o] = b[o] - mean * sc;
    }
}

// ---------------- column stats over BN rows (dec path) ----------------
__global__ void colstats_kernel(const float* __restrict__ X, int O, float invCnt,
                                const float* __restrict__ g, const float* __restrict__ b,
                                int stage) {
    int o = blockIdx.x;
    __shared__ float r1[256], r2[256];
    float s1 = 0.0f, s2 = 0.0f;
    for (int r = threadIdx.x; r < BN_TOT; r += 256) {
        float v = X[(size_t)r*O + o];
        s1 += v; s2 += v*v;
    }
    r1[threadIdx.x] = s1; r2[threadIdx.x] = s2;
    __syncthreads();
    for (int s = 128; s > 0; s >>= 1) {
        if (threadIdx.x < s) {
            r1[threadIdx.x] += r1[threadIdx.x + s];
            r2[threadIdx.x] += r2[threadIdx.x + s];
        }
        __syncthreads();
    }
    if (threadIdx.x == 0) {
        float mean = r1[0] * invCnt;
        float var  = r2[0] * invCnt - mean*mean;
        float sc = g[o] * rsqrtf(var + 1e-5f);
        d_scaleA[stage][o] = sc;
        d_shiftA[stage][o] = b[o] - mean * sc;
    }
}

// ---------------- cat with fused affines ----------------
__global__ void cat_kernel(const float* __restrict__ G4, const float* __restrict__ Gdec,
                           float* __restrict__ cat) {
    int t = blockIdx.x * blockDim.x + threadIdx.x;
    if (t >= BN_TOT*304) return;
    int p = t / 304, c = t % 304;
    float v;
    if (c < 256)
        v = fmaxf(fmaf(G4[(size_t)p*512 + c], d_scaleA[3][c], d_shiftA[3][c]), 0.0f);
    else {
        int q = c - 256;
        v = fmaxf(fmaf(Gdec[(size_t)p*48 + q], d_scaleA[4][q], d_shiftA[4][q]), 0.0f);
    }
    cat[t] = v;
}

// ---------------- pooling ----------------
__global__ void pool_partial_kernel(const float* __restrict__ fused, float* __restrict__ pool) {
    int b = blockIdx.x, ch = blockIdx.y, o = threadIdx.x;
    int n0 = ch * 256;
    float mx = NEG_INF, sm = 0.0f;
    for (int i = 0; i < 256; ++i) {
        float v = fused[((size_t)(b*NN + n0 + i))*256 + o];
        mx = fmaxf(mx, v);
        sm += v;
    }
    pool[((size_t)(b*16 + ch))*512 + o]       = mx;
    pool[((size_t)(b*16 + ch))*512 + 256 + o] = sm;
}

__global__ void pool_combine_kernel(const float* __restrict__ pool, float* __restrict__ h) {
    int b = blockIdx.x, o = threadIdx.x;
    float mx = NEG_INF, sm = 0.0f;
    for (int c = 0; c < 16; ++c) {
        mx = fmaxf(mx, pool[((size_t)(b*16 + c))*512 + o]);
        sm += pool[((size_t)(b*16 + c))*512 + 256 + o];
    }
    h[b*512 + o]       = mx;
    h[b*512 + 256 + o] = sm * (1.0f / (float)NN);
}

// ---------------- classifier head ----------------
__global__ void head1_kernel(const float* __restrict__ w, const float* __restrict__ h,
                             float* __restrict__ y1) {
    int b = blockIdx.x, o = threadIdx.x;
    float acc = 0.0f;
    for (int c = 0; c < 512; ++c)
        acc = fmaf(w[o*512 + c], h[b*512 + c], acc);
    y1[b*256 + o] = acc;
}

__global__ void headbn_kernel(const float* __restrict__ y1, const float* __restrict__ g,
                              const float* __restrict__ b, float* __restrict__ h2) {
    int o = threadIdx.x;
    float v0 = y1[0*256 + o], v1 = y1[1*256 + o], v2 = y1[2*256 + o], v3 = y1[3*256 + o];
    float m = 0.25f * (v0 + v1 + v2 + v3);
    float q0 = v0 - m, q1 = v1 - m, q2 = v2 - m, q3 = v3 - m;
    float var = 0.25f * (q0*q0 + q1*q1 + q2*q2 + q3*q3);
    float sc = g[o] * rsqrtf(var + 1e-5f);
    float bo = b[o];
    h2[0*256 + o] = fmaxf(q0*sc + bo, 0.0f);
    h2[1*256 + o] = fmaxf(q1*sc + bo, 0.0f);
    h2[2*256 + o] = fmaxf(q2*sc + bo, 0.0f);
    h2[3*256 + o] = fmaxf(q3*sc + bo, 0.0f);
}

__global__ void head2_kernel(const float* __restrict__ w, const float* __restrict__ h2,
                             float* __restrict__ out) {
    int t = threadIdx.x;
    if (t >= 160) return;
    int b = t / 40, q = t % 40;
    float acc = 0.0f;
    for (int c = 0; c < 256; ++c)
        acc = fmaf(w[q*256 + c], h2[b*256 + c], acc);
    out[b*40 + q] = acc;
}

// ---------------- host driver ----------------
static float* getF(const void* sym) { void* p = nullptr; cudaGetSymbolAddress(&p, sym); return (float*)p; }

extern "C" void kernel_launch(void* const* d_in, const int* in_sizes, int n_in,
                              void* d_out, int out_size) {
    const float* x      = (const float*)d_in[0];
    const float* w1     = (const float*)d_in[2];
    const float* g1     = (const float*)d_in[3];
    const float* b1     = (const float*)d_in[4];
    const float* w2     = (const float*)d_in[5];
    const float* g2     = (const float*)d_in[6];
    const float* b2     = (const float*)d_in[7];
    const float* w3     = (const float*)d_in[8];
    const float* g3     = (const float*)d_in[9];
    const float* b3     = (const float*)d_in[10];
    const float* w4     = (const float*)d_in[11];
    const float* g4     = (const float*)d_in[12];
    const float* b4     = (const float*)d_in[13];
    const float* dec_w  = (const float*)d_in[14];
    const float* dec_g  = (const float*)d_in[15];
    const float* dec_b  = (const float*)d_in[16];
    const float* fus_w  = (const float*)d_in[17];
    const float* cls_w1 = (const float*)d_in[18];
    const float* cls_g  = (const float*)d_in[19];
    const float* cls_b  = (const float*)d_in[20];
    const float* cls_w2 = (const float*)d_in[21];
    float* out = (float*)d_out;

    float* Xt   = getF(d_Xt);
    float* X2   = getF(d_x2);
    float* CD   = getF(d_candD);
    float* G1   = getF(d_G1);
    float* G2   = getF(d_G2);
    float* G3   = getF(d_G3);
    float* G4   = getF(d_G4);
    float* GD   = getF(d_Gdec);
    float* CAT  = getF(d_cat);
    float* FUS  = getF(d_fused);
    float* P1   = getF(d_part1);
    float* P2   = getF(d_part2);
    float* POOL = getF(d_pool);
    float* H    = getF(d_h);
    float* Y1   = getF(d_y1);
    float* H2   = getF(d_h2);
    void* ip = nullptr; cudaGetSymbolAddress(&ip, d_idx);
    int* IDX = (int*)ip;
    void* cp = nullptr; cudaGetSymbolAddress(&cp, d_candI);
    int* CI = (int*)cp;

    static int attr_done = 0;
    if (!attr_done) {
        cudaFuncSetAttribute(mma_gemm, cudaFuncAttributeMaxDynamicSharedMemorySize, MMA_SMEM);
        attr_done = 1;
    }

    // prep + knn (chunked)
    prep_kernel<<<(BN_TOT + 255)/256, 256>>>(x, Xt, X2);
    knn_part_kernel<<<dim3(BB, NN/128, KS), 128>>>(Xt, X2, CD, CI);
    knn_merge_kernel<<<(BN_TOT + 255)/256, 256>>>(CD, CI, IDX);

    // conv1 (Kc=3 special)
    conv1_kernel<<<BN_TOT*128/4/256, 256>>>(Xt, w1, G1);
    edge_kernel<<<1024, 256>>>(G1, IDX, 64, P1, P2);
    reduce_stats_kernel<<<64, 256>>>(P1, P2, g1, b1, 64, 1.0f/(float)(BN_TOT*KNN), 0);

    // conv2: A = relu(aff0(G1[:, :64])), W folded from w2 (128 x 128)
    mma_gemm<<<dim3(BN_TOT/BM, 2), 256, MMA_SMEM>>>(G1, 128, w2, 1, 128, G2, 256, 64, 0);
    edge_kernel<<<1024, 256>>>(G2, IDX, 128, P1, P2);
    reduce_stats_kernel<<<128, 256>>>(P1, P2, g2, b2, 128, 1.0f/(float)(BN_TOT*KNN), 1);

    // conv3
    mma_gemm<<<dim3(BN_TOT/BM, 4), 256, MMA_SMEM>>>(G2, 256, w3, 1, 256, G3, 512, 128, 1);
    edge_kernel<<<1024, 256>>>(G3, IDX, 256, P1, P2);
    reduce_stats_kernel<<<256, 256>>>(P1, P2, g3, b3, 256, 1.0f/(float)(BN_TOT*KNN), 2);

    // conv4
    mma_gemm<<<dim3(BN_TOT/BM, 4), 256, MMA_SMEM>>>(G3, 512, w4, 1, 256, G4, 512, 256, 2);
    edge_kernel<<<1024, 256>>>(G4, IDX, 256, P1, P2);
    reduce_stats_kernel<<<256, 256>>>(P1, P2, g4, b4, 256, 1.0f/(float)(BN_TOT*KNN), 3);

    // decoder: Gdec = relu(aff0(G1[:, :64])) @ dec_w^T
    mma_gemm<<<dim3(BN_TOT/BM, 1), 256, MMA_SMEM>>>(G1, 128, dec_w, 0, 0, GD, 48, 64, 0);
    colstats_kernel<<<48, 256>>>(GD, 48, 1.0f/(float)BN_TOT, dec_g, dec_b, 4);

    // fused concat (applies aff3 on G4 part, aff4 on dec part)
    cat_kernel<<<(BN_TOT*304 + 255)/256, 256>>>(G4, GD, CAT);
    mma_gemm<<<dim3(BN_TOT/BM, 2), 256, MMA_SMEM>>>(CAT, 304, fus_w, 0, 0, FUS, 256, 304, -1);

    // pool + head
    pool_partial_kernel<<<dim3(4, 16), 256>>>(FUS, POOL);
    pool_combine_kernel<<<4, 256>>>(POOL, H);
    head1_kernel<<<4, 256>>>(cls_w1, H, Y1);
    headbn_kernel<<<1, 256>>>(Y1, cls_g, cls_b, H2);
    head2_kernel<<<1, 160>>>(cls_w2, H2, out);
}

// round 11
// speedup vs baseline: 2.1051x; 1.0323x over previous
#include <cuda_runtime.h>
#include <cstdint>

#define BB 4
#define NN 4096
#define KNN 9
#define KS 4
#define CHUNK (NN/KS)
#define BN_TOT (BB*NN)
#define NEG_INF (-3.402823466e38f)

// ---------------- device scratch ----------------
__device__ float d_Xt[BN_TOT*3];
__device__ float d_x2[BN_TOT];
__device__ int   d_idx[BN_TOT*KNN];
__device__ float d_candD[BN_TOT*KS*KNN];
__device__ int   d_candI[BN_TOT*KS*KNN];
__device__ float d_G1[BN_TOT*128];
__device__ float d_G2[BN_TOT*256];
__device__ float d_G3[BN_TOT*512];
__device__ float d_G4[BN_TOT*512];
__device__ float d_Gdec[BN_TOT*48];
__device__ float d_fused[BN_TOT*256];
__device__ float d_part1[1024*256];
__device__ float d_part2[1024*256];
__device__ __align__(16) float d_scaleA[5][256];
__device__ __align__(16) float d_shiftA[5][256];
__device__ __align__(16) uint32_t d_Ah[BN_TOT*160];   // packed bf16x2 hi (max K2=160)
__device__ __align__(16) uint32_t d_Al[BN_TOT*160];   // packed bf16x2 lo
__device__ __align__(16) uint32_t d_Wh[512*160];
__device__ __align__(16) uint32_t d_Wl[512*160];
__device__ float d_pool[4*16*512];
__device__ float d_h[4*512];
__device__ float d_y1[4*256];
__device__ float d_h2[4*256];

// ---------------- helpers ----------------
__device__ __forceinline__ uint32_t pack_bf16(float a0, float a1) {
    uint32_t r; asm("cvt.rn.bf16x2.f32 %0, %1, %2;" : "=r"(r) : "f"(a1), "f"(a0));
    return r;
}
// split two floats into (hi bf16x2, lo bf16x2)
__device__ __forceinline__ void split_bf16(float v0, float v1, uint32_t& h, uint32_t& l) {
    h = pack_bf16(v0, v1);
    l = pack_bf16(v0 - __uint_as_float(h << 16),
                  v1 - __uint_as_float(h & 0xffff0000u));
}
__device__ __forceinline__ void mma16(float* d, uint32_t a0, uint32_t a1, uint32_t a2, uint32_t a3,
                                      uint32_t b0, uint32_t b1) {
    asm volatile(
        "mma.sync.aligned.m16n8k16.row.col.f32.bf16.bf16.f32 "
        "{%0,%1,%2,%3},{%4,%5,%6,%7},{%8,%9},{%0,%1,%2,%3};"
        : "+f"(d[0]), "+f"(d[1]), "+f"(d[2]), "+f"(d[3])
        : "r"(a0), "r"(a1), "r"(a2), "r"(a3), "r"(b0), "r"(b1));
}
__device__ __forceinline__ uint32_t smem_u32(const void* p) {
    uint32_t a;
    asm("{ .reg .u64 t; cvta.to.shared.u64 t, %1; cvt.u32.u64 %0, t; }" : "=r"(a) : "l"(p));
    return a;
}
#define LDSM4(r0,r1,r2,r3,addr) \
    asm volatile("ldmatrix.sync.aligned.m8n8.x4.shared.b16 {%0,%1,%2,%3}, [%4];" \
        : "=r"(r0),"=r"(r1),"=r"(r2),"=r"(r3) : "r"(addr))
#define CP_ASYNC16(s, g) \
    asm volatile("cp.async.cg.shared.global [%0], [%1], 16;" :: "r"(s), "l"(g))
#define CP_COMMIT()  asm volatile("cp.async.commit_group;" ::: "memory")
#define CP_WAIT1()   asm volatile("cp.async.wait_group 1;" ::: "memory")

// ---------------- prep ----------------
__global__ void prep_kernel(const float* __restrict__ x, float* __restrict__ Xt,
                            float* __restrict__ x2) {
    int t = blockIdx.x * blockDim.x + threadIdx.x;
    if (t >= BN_TOT) return;
    int b = t / NN, n = t % NN;
    float a0 = x[(b*3+0)*NN + n];
    float a1 = x[(b*3+1)*NN + n];
    float a2 = x[(b*3+2)*NN + n];
    Xt[t*3+0] = a0; Xt[t*3+1] = a1; Xt[t*3+2] = a2;
    x2[t] = a0*a0 + a1*a1 + a2*a2;
}

// ---------------- knn ----------------
__global__ void knn_part_kernel(const float* __restrict__ Xt, const float* __restrict__ x2,
                                float* __restrict__ candD, int* __restrict__ candI) {
    __shared__ float sx[CHUNK], sy[CHUNK], sz[CHUNK], s2[CHUNK];
    int b  = blockIdx.x;
    int n  = blockIdx.y * blockDim.x + threadIdx.x;
    int cs = blockIdx.z;
    int m0 = cs * CHUNK;
    const float* Xb = Xt + (size_t)b*NN*3;
    for (int t = threadIdx.x; t < CHUNK; t += blockDim.x) {
        int m = m0 + t;
        sx[t] = Xb[m*3+0];
        sy[t] = Xb[m*3+1];
        sz[t] = Xb[m*3+2];
        s2[t] = x2[b*NN + m];
    }
    __syncthreads();
    float px = Xb[n*3+0], py = Xb[n*3+1], pz = Xb[n*3+2], p2 = x2[b*NN + n];
    float bd[KNN]; int bi[KNN];
#pragma unroll
    for (int j = 0; j < KNN; ++j) { bd[j] = 1e30f; bi[j] = 0; }
#pragma unroll 4
    for (int mm = 0; mm < CHUNK; ++mm) {
        float dot = px*sx[mm] + py*sy[mm] + pz*sz[mm];
        float d = p2 + s2[mm] - 2.0f*dot;
        int m = m0 + mm;
        if (m == n) d = 1e30f;
        if (d < bd[KNN-1]) {
            float vd = d; int vi = m;
#pragma unroll
            for (int j = 0; j < KNN; ++j) {
                if (vd < bd[j]) {
                    float td = bd[j]; bd[j] = vd; vd = td;
                    int   ti = bi[j]; bi[j] = vi; vi = ti;
                }
            }
        }
    }
    size_t base = ((size_t)(b*NN + n)*KS + cs)*KNN;
#pragma unroll
    for (int j = 0; j < KNN; ++j) {
        candD[base + j] = bd[j];
        candI[base + j] = bi[j];
    }
}

__global__ void knn_merge_kernel(const float* __restrict__ candD, const int* __restrict__ candI,
                                 int* __restrict__ idxOut) {
    int t = blockIdx.x * blockDim.x + threadIdx.x;
    if (t >= BN_TOT) return;
    int b = t / NN;
    float bd[KNN]; int bi[KNN];
#pragma unroll
    for (int j = 0; j < KNN; ++j) { bd[j] = 1e30f; bi[j] = 0; }
    size_t base = (size_t)t*KS*KNN;
    for (int c = 0; c < KS*KNN; ++c) {
        float d = candD[base + c];
        int   m = candI[base + c];
        if (d < bd[KNN-1]) {
            float vd = d; int vi = m;
#pragma unroll
            for (int j = 0; j < KNN; ++j) {
                if (vd < bd[j]) {
                    float td = bd[j]; bd[j] = vd; vd = td;
                    int   ti = bi[j]; bi[j] = vi; vi = ti;
                }
            }
        }
    }
#pragma unroll
    for (int j = 0; j < KNN; ++j)
        idxOut[t*KNN + j] = b*NN + bi[j];
}

// ---------------- conv1 (Kc=3) ----------------
__global__ void conv1_kernel(const float* __restrict__ Xt, const float* __restrict__ w1,
                             float* __restrict__ G) {
    __shared__ float cw0[128], cw1[128], cw2[128];
    int tid = threadIdx.x;
    if (tid < 128) {
        if (tid < 64) {
            cw0[tid] = w1[tid*6+0] - w1[tid*6+3];
            cw1[tid] = w1[tid*6+1] - w1[tid*6+4];
            cw2[tid] = w1[tid*6+2] - w1[tid*6+5];
        } else {
            int q = tid - 64;
            cw0[tid] = w1[q*6+3]; cw1[tid] = w1[q*6+4]; cw2[tid] = w1[q*6+5];
        }
    }
    __syncthreads();
    int t4 = blockIdx.x * blockDim.x + tid;
    if (t4 >= BN_TOT*128/4) return;
    int t = t4 * 4;
    int p = t >> 7, o = t & 127;
    float x0 = Xt[p*3+0], x1 = Xt[p*3+1], x2 = Xt[p*3+2];
    float4 r;
    r.x = cw0[o+0]*x0 + cw1[o+0]*x1 + cw2[o+0]*x2;
    r.y = cw0[o+1]*x0 + cw1[o+1]*x1 + cw2[o+1]*x2;
    r.z = cw0[o+2]*x0 + cw1[o+2]*x1 + cw2[o+2]*x2;
    r.w = cw0[o+3]*x0 + cw1[o+3]*x1 + cw2[o+3]*x2;
    *(float4*)&G[t] = r;
}

// ---------------- preconvert A: relu(aff(src)) -> packed bf16 hi/lo ----------------
__global__ void convA_kernel(const float* __restrict__ src, int lda, int Kc, int K2,
                             int stage, uint32_t* __restrict__ Ah, uint32_t* __restrict__ Al) {
    int t = blockIdx.x * blockDim.x + threadIdx.x;
    if (t >= BN_TOT*K2) return;
    int p = t / K2, k2 = t % K2;
    int k = 2*k2;
    float v0 = 0.f, v1 = 0.f;
    if (k < Kc) {
        v0 = src[(size_t)p*lda + k];
        v1 = src[(size_t)p*lda + k + 1];
        if (stage >= 0) {
            v0 = fmaxf(fmaf(v0, d_scaleA[stage][k],   d_shiftA[stage][k]),   0.0f);
            v1 = fmaxf(fmaf(v1, d_scaleA[stage][k+1], d_shiftA[stage][k+1]), 0.0f);
        }
    }
    uint32_t h, l; split_bf16(v0, v1, h, l);
    Ah[t] = h; Al[t] = l;
}

// ---------------- preconvert W -> packed bf16 hi/lo (with wmode fold + padding) ----------------
__global__ void convW_kernel(const float* __restrict__ W, int wmode, int O, int Nc,
                             int Kc, int K2, int Npad,
                             uint32_t* __restrict__ Wh, uint32_t* __restrict__ Wl) {
    int t = blockIdx.x * blockDim.x + threadIdx.x;
    if (t >= Npad*K2) return;
    int n = t / K2, k2 = t % K2;
    int k = 2*k2;
    float v0 = 0.f, v1 = 0.f;
    if (k < Kc) {
        if (wmode == 1) {
            if (n < O) {
                v0 = W[(size_t)n*2*Kc + k]     - W[(size_t)n*2*Kc + Kc + k];
                v1 = W[(size_t)n*2*Kc + k + 1] - W[(size_t)n*2*Kc + Kc + k + 1];
            } else if (n < 2*O) {
                v0 = W[(size_t)(n-O)*2*Kc + Kc + k];
                v1 = W[(size_t)(n-O)*2*Kc + Kc + k + 1];
            }
        } else if (n < Nc) {
            v0 = W[(size_t)n*Kc + k];
            v1 = W[(size_t)n*Kc + k + 1];
        }
    }
    uint32_t h, l; split_bf16(v0, v1, h, l);
    Wh[t] = h; Wl[t] = l;
}

// ---------------- cat: fused affines -> packed bf16 (K2=160, k>=304 zero) ----------------
__global__ void convCat_kernel(const float* __restrict__ G4, const float* __restrict__ Gdec,
                               uint32_t* __restrict__ Ah, uint32_t* __restrict__ Al) {
    int t = blockIdx.x * blockDim.x + threadIdx.x;
    if (t >= BN_TOT*160) return;
    int p = t / 160, k2 = t % 160;
    int k = 2*k2;
    float v0 = 0.f, v1 = 0.f;
    if (k < 256) {
        v0 = fmaxf(fmaf(G4[(size_t)p*512 + k],   d_scaleA[3][k],   d_shiftA[3][k]),   0.0f);
        v1 = fmaxf(fmaf(G4[(size_t)p*512 + k+1], d_scaleA[3][k+1], d_shiftA[3][k+1]), 0.0f);
    } else if (k < 304) {
        int q = k - 256;
        v0 = fmaxf(fmaf(Gdec[(size_t)p*48 + q],   d_scaleA[4][q],   d_shiftA[4][q]),   0.0f);
        if (q + 1 < 48)
            v1 = fmaxf(fmaf(Gdec[(size_t)p*48 + q+1], d_scaleA[4][q+1], d_shiftA[4][q+1]), 0.0f);
    }
    uint32_t h, l; split_bf16(v0, v1, h, l);
    Ah[t] = h; Al[t] = l;
}

// ---------------- bf16x3 GEMM: cp.async + ldmatrix + mma.sync ----------------
// C[M x Nc] = A * W^T from pre-packed hi/lo bf16x2 arrays (row stride sK2 u32).
// Block tile 128x128, BK=32 (16 u32/row/iter), double buffered.
// smem row stride 20 u32 (80B) -> ldmatrix phases conflict-free.
#define GS_ROW 20
#define GS_ARR (128*GS_ROW)            // 2560 u32 per array
#define GS_BUF (4*GS_ARR)              // 10240 u32 per buffer
#define GEMM_SMEM (2*GS_BUF*4)         // 81920 bytes

__global__ __launch_bounds__(256, 2)
void bf_gemm(const uint32_t* __restrict__ Ah, const uint32_t* __restrict__ Al, int sK2,
             const uint32_t* __restrict__ Wh, const uint32_t* __restrict__ Wl,
             float* __restrict__ C, int Nc, int nIter) {
    extern __shared__ uint32_t sm[];
    uint32_t sbase = smem_u32(sm);

    int tid = threadIdx.x;
    int lane = tid & 31, wid = tid >> 5;
    int wm = wid >> 2, wn = wid & 3;
    int g = lane >> 2, tig = lane & 3;
    int bm = blockIdx.x * 128;
    int bn = blockIdx.y * 128;

    float d[4][4][4];
#pragma unroll
    for (int i = 0; i < 4; ++i)
#pragma unroll
        for (int j = 0; j < 4; ++j)
#pragma unroll
            for (int q = 0; q < 4; ++q) d[i][j][q] = 0.0f;

    // cp.async chunk mapping: 2048 chunks of 16B; 8 per thread
#define ISSUE_LOADS(IT, BUFO)                                                   \
    {                                                                           \
        int k2o = (IT)*16;                                                      \
        _Pragma("unroll")                                                       \
        for (int i = 0; i < 8; ++i) {                                           \
            int c   = tid + i*256;                                              \
            int arr = c >> 9;                                                   \
            int rr  = (c & 511) >> 2;                                           \
            int col = c & 3;                                                    \
            const uint32_t* gp;                                                 \
            if (arr == 0)      gp = Ah + (size_t)(bm + rr)*sK2 + k2o + col*4;   \
            else if (arr == 1) gp = Al + (size_t)(bm + rr)*sK2 + k2o + col*4;   \
            else if (arr == 2) gp = Wh + (size_t)(bn + rr)*sK2 + k2o + col*4;   \
            else               gp = Wl + (size_t)(bn + rr)*sK2 + k2o + col*4;   \
            uint32_t sa = sbase + ((BUFO) + arr*GS_ARR + rr*GS_ROW + col*4)*4;  \
            CP_ASYNC16(sa, gp);                                                 \
        }                                                                       \
    }

    ISSUE_LOADS(0, 0)
    CP_COMMIT();

    int aRow = ((lane >> 3) & 1)*8 + (lane & 7);
    int aChk = lane >> 4;
    int bRow = ((lane >> 4) & 1)*8 + (lane & 7);
    int bChk = (lane >> 3) & 1;

    for (int it = 0; it < nIter; ++it) {
        int bufo = (it & 1) * GS_BUF;
        int nxto = ((it + 1) & 1) * GS_BUF;
        if (it + 1 < nIter) ISSUE_LOADS(it + 1, nxto)
        CP_COMMIT();
        CP_WAIT1();
        __syncthreads();

        uint32_t ahB = sbase + (bufo + 0*GS_ARR)*4;
        uint32_t alB = sbase + (bufo + 1*GS_ARR)*4;
        uint32_t bhB = sbase + (bufo + 2*GS_ARR)*4;
        uint32_t blB = sbase + (bufo + 3*GS_ARR)*4;

#pragma unroll
        for (int ks = 0; ks < 2; ++ks) {
            uint32_t bh[4][2], bl[4][2];
#pragma unroll
            for (int p = 0; p < 2; ++p) {
                uint32_t off = ((wn*32 + p*16 + bRow)*GS_ROW + (ks*2 + bChk)*4)*4;
                LDSM4(bh[2*p][0], bh[2*p][1], bh[2*p+1][0], bh[2*p+1][1], bhB + off);
                LDSM4(bl[2*p][0], bl[2*p][1], bl[2*p+1][0], bl[2*p+1][1], blB + off);
            }
#pragma unroll
            for (int mt = 0; mt < 4; ++mt) {
                uint32_t a0, a1, a2, a3, l0, l1, l2, l3;
                uint32_t off = ((wm*64 + mt*16 + aRow)*GS_ROW + (ks*2 + aChk)*4)*4;
                LDSM4(a0, a1, a2, a3, ahB + off);
                LDSM4(l0, l1, l2, l3, alB + off);
#pragma unroll
                for (int nt = 0; nt < 4; ++nt) {
                    mma16(d[mt][nt], a0, a1, a2, a3, bl[nt][0], bl[nt][1]);
                    mma16(d[mt][nt], a0, a1, a2, a3, bh[nt][0], bh[nt][1]);
                    mma16(d[mt][nt], l0, l1, l2, l3, bh[nt][0], bh[nt][1]);
                }
            }
        }
        __syncthreads();
    }

#pragma unroll
    for (int mt = 0; mt < 4; ++mt) {
        int row = bm + wm*64 + mt*16 + g;
#pragma unroll
        for (int nt = 0; nt < 4; ++nt) {
            int col = bn + wn*32 + nt*8 + tig*2;
            if (col < Nc) {
                *(float2*)&C[(size_t)row*Nc + col]     = make_float2(d[mt][nt][0], d[mt][nt][1]);
                *(float2*)&C[(size_t)(row+8)*Nc + col] = make_float2(d[mt][nt][2], d[mt][nt][3]);
            }
        }
    }
#undef ISSUE_LOADS
}

// ---------------- edge pass ----------------
__global__ void edge_kernel(float* __restrict__ G, const int* __restrict__ idx,
                            int O, float* __restrict__ part1, float* __restrict__ part2) {
    int tid = threadIdx.x;
    int o = tid % O;
    int pr = tid / O;
    int R = 256 / O;
    int blk = blockIdx.x;
    int p0 = blk * 16;
    __shared__ int sidx[16*KNN];
    for (int t = tid; t < 16*KNN; t += 256)
        sidx[t] = idx[p0*KNN + t];
    __syncthreads();
    int S = 2*O;
    float s1 = 0.0f, s2 = 0.0f;
    for (int pp = pr; pp < 16; pp += R) {
        int p = p0 + pp;
        float u = G[(size_t)p*S + o];
        float zmax = NEG_INF;
#pragma unroll
        for (int k = 0; k < KNN; ++k) {
            int j = sidx[pp*KNN + k];
            float z = G[(size_t)j*S + O + o];
            float v = u + z;
            zmax = fmaxf(zmax, z);
            s1 += v;
            s2 += v*v;
        }
        G[(size_t)p*S + o] = u + zmax;
    }
    __shared__ float red1[256], red2[256];
    red1[tid] = s1; red2[tid] = s2;
    __syncthreads();
    for (int r = R >> 1; r > 0; r >>= 1) {
        if (pr < r) {
            red1[tid] += red1[tid + r*O];
            red2[tid] += red2[tid + r*O];
        }
        __syncthreads();
    }
    if (pr == 0) {
        part1[blk*O + o] = red1[tid];
        part2[blk*O + o] = red2[tid];
    }
}

// ---------------- stats ----------------
__global__ void reduce_stats_kernel(const float* __restrict__ part1,
                                    const float* __restrict__ part2,
                                    const float* __restrict__ g, const float* __restrict__ b,
                                    int O, float invCnt, int stage) {
    int o = blockIdx.x;
    int tid = threadIdx.x;
    float s1 = 0.0f, s2 = 0.0f;
    for (int i = tid; i < 1024; i += 256) {
        s1 += part1[(size_t)i*O + o];
        s2 += part2[(size_t)i*O + o];
    }
    __shared__ float r1[256], r2[256];
    r1[tid] = s1; r2[tid] = s2;
    __syncthreads();
    for (int s = 128; s > 0; s >>= 1) {
        if (tid < s) { r1[tid] += r1[tid + s]; r2[tid] += r2[tid + s]; }
        __syncthreads();
    }
    if (tid == 0) {
        float mean = r1[0] * invCnt;
        float var  = r2[0] * invCnt - mean*mean;
        float sc = g[o] * rsqrtf(var + 1e-5f);
        d_scaleA[stage][o] = sc;
        d_shiftA[stage][o] = b[o] - mean * sc;
    }
}

__global__ void colstats_kernel(const float* __restrict__ X, int O, float invCnt,
                                const float* __restrict__ g, const float* __restrict__ b,
                                int stage) {
    int o = blockIdx.x;
    __shared__ float r1[256], r2[256];
    float s1 = 0.0f, s2 = 0.0f;
    for (int r = threadIdx.x; r < BN_TOT; r += 256) {
        float v = X[(size_t)r*O + o];
        s1 += v; s2 += v*v;
    }
    r1[threadIdx.x] = s1; r2[threadIdx.x] = s2;
    __syncthreads();
    for (int s = 128; s > 0; s >>= 1) {
        if (threadIdx.x < s) {
            r1[threadIdx.x] += r1[threadIdx.x + s];
            r2[threadIdx.x] += r2[threadIdx.x + s];
        }
        __syncthreads();
    }
    if (threadIdx.x == 0) {
        float mean = r1[0] * invCnt;
        float var  = r2[0] * invCnt - mean*mean;
        float sc = g[o] * rsqrtf(var + 1e-5f);
        d_scaleA[stage][o] = sc;
        d_shiftA[stage][o] = b[o] - mean * sc;
    }
}

// ---------------- pooling ----------------
__global__ void pool_partial_kernel(const float* __restrict__ fused, float* __restrict__ pool) {
    int b = blockIdx.x, ch = blockIdx.y, o = threadIdx.x;
    int n0 = ch * 256;
    float mx = NEG_INF, sm = 0.0f;
    for (int i = 0; i < 256; ++i) {
        float v = fused[((size_t)(b*NN + n0 + i))*256 + o];
        mx = fmaxf(mx, v);
        sm += v;
    }
    pool[((size_t)(b*16 + ch))*512 + o]       = mx;
    pool[((size_t)(b*16 + ch))*512 + 256 + o] = sm;
}

__global__ void pool_combine_kernel(const float* __restrict__ pool, float* __restrict__ h) {
    int b = blockIdx.x, o = threadIdx.x;
    float mx = NEG_INF, sm = 0.0f;
    for (int c = 0; c < 16; ++c) {
        mx = fmaxf(mx, pool[((size_t)(b*16 + c))*512 + o]);
        sm += pool[((size_t)(b*16 + c))*512 + 256 + o];
    }
    h[b*512 + o]       = mx;
    h[b*512 + 256 + o] = sm * (1.0f / (float)NN);
}

// ---------------- classifier head ----------------
__global__ void head1_kernel(const float* __restrict__ w, const float* __restrict__ h,
                             float* __restrict__ y1) {
    int b = blockIdx.x, o = threadIdx.x;
    float acc = 0.0f;
    for (int c = 0; c < 512; ++c)
        acc = fmaf(w[o*512 + c], h[b*512 + c], acc);
    y1[b*256 + o] = acc;
}

__global__ void headbn_kernel(const float* __restrict__ y1, const float* __restrict__ g,
                              const float* __restrict__ b, float* __restrict__ h2) {
    int o = threadIdx.x;
    float v0 = y1[0*256 + o], v1 = y1[1*256 + o], v2 = y1[2*256 + o], v3 = y1[3*256 + o];
    float m = 0.25f * (v0 + v1 + v2 + v3);
    float q0 = v0 - m, q1 = v1 - m, q2 = v2 - m, q3 = v3 - m;
    float var = 0.25f * (q0*q0 + q1*q1 + q2*q2 + q3*q3);
    float sc = g[o] * rsqrtf(var + 1e-5f);
    float bo = b[o];
    h2[0*256 + o] = fmaxf(q0*sc + bo, 0.0f);
    h2[1*256 + o] = fmaxf(q1*sc + bo, 0.0f);
    h2[2*256 + o] = fmaxf(q2*sc + bo, 0.0f);
    h2[3*256 + o] = fmaxf(q3*sc + bo, 0.0f);
}

__global__ void head2_kernel(const float* __restrict__ w, const float* __restrict__ h2,
                             float* __restrict__ out) {
    int t = threadIdx.x;
    if (t >= 160) return;
    int b = t / 40, q = t % 40;
    float acc = 0.0f;
    for (int c = 0; c < 256; ++c)
        acc = fmaf(w[q*256 + c], h2[b*256 + c], acc);
    out[b*40 + q] = acc;
}

// ---------------- host driver ----------------
static float* getF(const void* sym) { void* p = nullptr; cudaGetSymbolAddress(&p, sym); return (float*)p; }
static uint32_t* getU(const void* sym) { void* p = nullptr; cudaGetSymbolAddress(&p, sym); return (uint32_t*)p; }

extern "C" void kernel_launch(void* const* d_in, const int* in_sizes, int n_in,
                              void* d_out, int out_size) {
    const float* x      = (const float*)d_in[0];
    const float* w1     = (const float*)d_in[2];
    const float* g1     = (const float*)d_in[3];
    const float* b1     = (const float*)d_in[4];
    const float* w2     = (const float*)d_in[5];
    const float* g2     = (const float*)d_in[6];
    const float* b2     = (const float*)d_in[7];
    const float* w3     = (const float*)d_in[8];
    const float* g3     = (const float*)d_in[9];
    const float* b3     = (const float*)d_in[10];
    const float* w4     = (const float*)d_in[11];
    const float* g4     = (const float*)d_in[12];
    const float* b4     = (const float*)d_in[13];
    const float* dec_w  = (const float*)d_in[14];
    const float* dec_g  = (const float*)d_in[15];
    const float* dec_b  = (const float*)d_in[16];
    const float* fus_w  = (const float*)d_in[17];
    const float* cls_w1 = (const float*)d_in[18];
    const float* cls_g  = (const float*)d_in[19];
    const float* cls_b  = (const float*)d_in[20];
    const float* cls_w2 = (const float*)d_in[21];
    float* out = (float*)d_out;

    float* Xt   = getF(d_Xt);
    float* X2   = getF(d_x2);
    float* CD   = getF(d_candD);
    float* G1   = getF(d_G1);
    float* G2   = getF(d_G2);
    float* G3   = getF(d_G3);
    float* G4   = getF(d_G4);
    float* GD   = getF(d_Gdec);
    float* FUS  = getF(d_fused);
    float* P1   = getF(d_part1);
    float* P2   = getF(d_part2);
    float* POOL = getF(d_pool);
    float* H    = getF(d_h);
    float* Y1   = getF(d_y1);
    float* H2   = getF(d_h2);
    uint32_t* AH = getU(d_Ah);
    uint32_t* AL = getU(d_Al);
    uint32_t* WH = getU(d_Wh);
    uint32_t* WL = getU(d_Wl);
    void* ip = nullptr; cudaGetSymbolAddress(&ip, d_idx);
    int* IDX = (int*)ip;
    void* cp = nullptr; cudaGetSymbolAddress(&cp, d_candI);
    int* CI = (int*)cp;

    static int attr_done = 0;
    if (!attr_done) {
        cudaFuncSetAttribute(bf_gemm, cudaFuncAttributeMaxDynamicSharedMemorySize, GEMM_SMEM);
        attr_done = 1;
    }

    // prep + knn
    prep_kernel<<<(BN_TOT + 255)/256, 256>>>(x, Xt, X2);
    knn_part_kernel<<<dim3(BB, NN/128, KS), 128>>>(Xt, X2, CD, CI);
    knn_merge_kernel<<<(BN_TOT + 255)/256, 256>>>(CD, CI, IDX);

    // conv1
    conv1_kernel<<<BN_TOT*128/4/256, 256>>>(Xt, w1, G1);
    edge_kernel<<<1024, 256>>>(G1, IDX, 64, P1, P2);
    reduce_stats_kernel<<<64, 256>>>(P1, P2, g1, b1, 64, 1.0f/(float)(BN_TOT*KNN), 0);

    // stage0 activation -> packed (shared by conv2 + dec)
    convA_kernel<<<(BN_TOT*32 + 255)/256, 256>>>(G1, 128, 64, 32, 0, AH, AL);

    // conv2: Kpad=64 (2 iters), Npad=256
    convW_kernel<<<(256*32 + 255)/256, 256>>>(w2, 1, 128, 256, 64, 32, 256, WH, WL);
    bf_gemm<<<dim3(BN_TOT/128, 2), 256, GEMM_SMEM>>>(AH, AL, 32, WH, WL, G2, 256, 2);

    // decoder (same packed A): Npad=128
    convW_kernel<<<(128*32 + 255)/256, 256>>>(dec_w, 0, 0, 48, 64, 32, 128, WH, WL);
    bf_gemm<<<dim3(BN_TOT/128, 1), 256, GEMM_SMEM>>>(AH, AL, 32, WH, WL, GD, 48, 2);
    colstats_kernel<<<48, 256>>>(GD, 48, 1.0f/(float)BN_TOT, dec_g, dec_b, 4);

    edge_kernel<<<1024, 256>>>(G2, IDX, 128, P1, P2);
    reduce_stats_kernel<<<128, 256>>>(P1, P2, g2, b2, 128, 1.0f/(float)(BN_TOT*KNN), 1);

    // conv3: Kpad=128 (4 iters), Npad=512
    convA_kernel<<<(BN_TOT*64 + 255)/256, 256>>>(G2, 256, 128, 64, 1, AH, AL);
    convW_kernel<<<(512*64 + 255)/256, 256>>>(w3, 1, 256, 512, 128, 64, 512, WH, WL);
    bf_gemm<<<dim3(BN_TOT/128, 4), 256, GEMM_SMEM>>>(AH, AL, 64, WH, WL, G3, 512, 4);
    edge_kernel<<<1024, 256>>>(G3, IDX, 256, P1, P2);
    reduce_stats_kernel<<<256, 256>>>(P1, P2, g3, b3, 256, 1.0f/(float)(BN_TOT*KNN), 2);

    // conv4: Kpad=256 (8 iters), Npad=512
    convA_kernel<<<(BN_TOT*128 + 255)/256, 256>>>(G3, 512, 256, 128, 2, AH, AL);
    convW_kernel<<<(512*128 + 255)/256, 256>>>(w4, 1, 256, 512, 256, 128, 512, WH, WL);
    bf_gemm<<<dim3(BN_TOT/128, 4), 256, GEMM_SMEM>>>(AH, AL, 128, WH, WL, G4, 512, 8);
    edge_kernel<<<1024, 256>>>(G4, IDX, 256, P1, P2);
    reduce_stats_kernel<<<256, 256>>>(P1, P2, g4, b4, 256, 1.0f/(float)(BN_TOT*KNN), 3);

    // fusion: packed cat (Kpad=320, 10 iters), Npad=256
    convCat_kernel<<<(BN_TOT*160 + 255)/256, 256>>>(G4, GD, AH, AL);
    convW_kernel<<<(256*160 + 255)/256, 256>>>(fus_w, 0, 0, 256, 304, 160, 256, WH, WL);
    bf_gemm<<<dim3(BN_TOT/128, 2), 256, GEMM_SMEM>>>(AH, AL, 160, WH, WL, FUS, 256, 10);

    // pool + head
    pool_partial_kernel<<<dim3(4, 16), 256>>>(FUS, POOL);
    pool_combine_kernel<<<4, 256>>>(POOL, H);
    head1_kernel<<<4, 256>>>(cls_w1, H, Y1);
    headbn_kernel<<<1, 256>>>(Y1, cls_g, cls_b, H2);
    head2_kernel<<<1, 160>>>(cls_w2, H2, out);
}